// round 4
// baseline (speedup 1.0000x reference)
#include <cuda_runtime.h>
#include <cstdint>

// ============================ problem sizes ============================
#define BATCH   8192
#define INDIM   1024
#define OUTDIM  1024
#define DEG1    9
#define KD2     (INDIM * 8)         // 8192 (GEMM K, d=1..8; d=0 folded into bias)
#define TM      128                 // CTA M tile
#define TN      128                 // CTA N tile
#define KC      32                  // K chunk per stage = 4 inputs x 8 degrees
#define NITER   (KD2 / KC)          // 256
#define NTHREADS 128                // 4 warps, each 64x64

#define AST  36                     // A row stride (words)
#define BST  36                     // B row stride
#define TST  36                     // t row stride

// __device__ scratch (static: allocation-guard safe)
__device__ float g_Bt[(size_t)OUTDIM * KD2];    // Bt[o][i*8+(d-1)], tf32 bits
__device__ float g_t[(size_t)BATCH * INDIM];    // clip(tanh(x))
__device__ float g_bias[OUTDIM];                // sum_i C[i][o][0]

// ============================ helpers ==================================
__device__ __forceinline__ uint32_t f32_to_tf32(float x) {
    uint32_t u;
    asm("cvt.rna.tf32.f32 %0, %1;" : "=r"(u) : "f"(x));
    return u;
}
__device__ __forceinline__ void cp_async16(uint32_t smem_dst, const void* gsrc) {
    asm volatile("cp.async.cg.shared.global [%0], [%1], 16;"
                 :: "r"(smem_dst), "l"(gsrc) : "memory");
}
__device__ __forceinline__ void cp_commit() {
    asm volatile("cp.async.commit_group;" ::: "memory");
}
__device__ __forceinline__ void cp_wait0() {
    asm volatile("cp.async.wait_group 0;" ::: "memory");
}
__device__ __forceinline__ uint32_t smem_u32(const void* p) {
    uint32_t a;
    asm("{ .reg .u64 t; cvta.to.shared.u64 t, %1; cvt.u32.u64 %0, t; }" : "=r"(a) : "l"(p));
    return a;
}
// mma.sync m16n8k8 row.col f32.tf32.tf32.f32
__device__ __forceinline__ void mma8(float* c, const uint32_t* a, const uint32_t* b) {
    asm volatile(
        "mma.sync.aligned.m16n8k8.row.col.f32.tf32.tf32.f32 "
        "{%0,%1,%2,%3}, {%4,%5,%6,%7}, {%8,%9}, {%0,%1,%2,%3};"
        : "+f"(c[0]), "+f"(c[1]), "+f"(c[2]), "+f"(c[3])
        : "r"(a[0]), "r"(a[1]), "r"(a[2]), "r"(a[3]), "r"(b[0]), "r"(b[1]));
}

// ======================= prep: t = clip(tanh(x)) =======================
__global__ __launch_bounds__(256)
void prep_t_kernel(const float* __restrict__ x) {
    size_t i4 = (size_t)blockIdx.x * 256 + threadIdx.x;
    const float4* src = (const float4*)x;
    float4* dst = (float4*)g_t;
    float4 v = src[i4];
    float4 r;
    r.x = fminf(fmaxf(tanhf(v.x), -0.999f), 0.999f);
    r.y = fminf(fmaxf(tanhf(v.y), -0.999f), 0.999f);
    r.z = fminf(fmaxf(tanhf(v.z), -0.999f), 0.999f);
    r.w = fminf(fmaxf(tanhf(v.w), -0.999f), 0.999f);
    dst[i4] = r;
}

// ============ prep: C[i,o,d>=1] -> Bt[o, i*8+d-1] (tf32) ===============
__global__ __launch_bounds__(256)
void prep_Bt_kernel(const float* __restrict__ C) {
    int idx = blockIdx.x * 256 + threadIdx.x;   // over INDIM*OUTDIM
    int i = idx >> 10;
    int o = idx & 1023;
    const float* src = C + (size_t)i * (OUTDIM * DEG1) + (size_t)o * DEG1;
    uint32_t* dst = (uint32_t*)(g_Bt + (size_t)o * KD2 + (size_t)i * 8);
#pragma unroll
    for (int d = 1; d < DEG1; d++) dst[d - 1] = f32_to_tf32(src[d]);
}

// ============ prep: bias[o] = sum_i C[i,o,0] (T_0 == 1) ================
__global__ __launch_bounds__(256)
void prep_bias_kernel(const float* __restrict__ C) {
    __shared__ float red[256];
    int o = blockIdx.x;
    int tid = threadIdx.x;
    float s = 0.0f;
#pragma unroll
    for (int i = tid; i < INDIM; i += 256)
        s += C[(size_t)i * (OUTDIM * DEG1) + (size_t)o * DEG1];
    red[tid] = s;
    __syncthreads();
#pragma unroll
    for (int w = 128; w > 0; w >>= 1) {
        if (tid < w) red[tid] += red[tid + w];
        __syncthreads();
    }
    if (tid == 0) g_bias[o] = red[0];
}

// ============================ main GEMM ================================
__global__ __launch_bounds__(NTHREADS, 2)
void cheby_gemm_kernel(float* __restrict__ out) {
    __shared__ uint32_t As[2][TM * AST];      // 2 x 18,432 B
    __shared__ uint32_t Bs[2][TN * BST];      // 2 x 18,432 B
    __shared__ float    Ts[TM * TST];         // 18,432 B   (total 90 KB)

    const int tid  = threadIdx.x;             // == producer row (0..127)
    const int wid  = tid >> 5;
    const int lane = tid & 31;
    const int gid  = lane >> 2;     // 0..7
    const int tg   = lane & 3;      // 0..3
    const int warp_m = wid & 1;     // 2 warps along M (64 rows each)
    const int warp_n = wid >> 1;    // 2 warps along N (64 cols each)
    const int m0 = blockIdx.x * TM;
    const int n0 = blockIdx.y * TN;

    float acc[4][8][4];
#pragma unroll
    for (int mf = 0; mf < 4; mf++)
#pragma unroll
        for (int nf = 0; nf < 8; nf++)
#pragma unroll
            for (int q = 0; q < 4; q++) acc[mf][nf][q] = 0.0f;

    // ---- prologue: kick B[0] (128 rows x 32 floats; thread = row) ----
    {
        const float* src = g_Bt + (size_t)(n0 + tid) * KD2;
        uint32_t dst = smem_u32(&Bs[0][tid * BST]);
#pragma unroll
        for (int q = 0; q < 8; q++) cp_async16(dst + q * 16, src + q * 4);
        cp_commit();
    }
    // ---- prologue: fill Ts(ib=0); thread = row ----
    {
        const float4* src = (const float4*)(g_t + (size_t)(m0 + tid) * INDIM);
        float4* dstv = (float4*)&Ts[tid * TST];
#pragma unroll
        for (int q = 0; q < 8; q++) dstv[q] = src[q];
    }
    __syncthreads();
    // ---- prologue: produce A[0] into buf 0 ----
    {
#pragma unroll
        for (int e = 0; e < 4; e++) {
            float t = Ts[tid * TST + e];
            float t2 = t + t;
            uint32_t v[8];
            v[0] = f32_to_tf32(t);
            float u0 = 1.0f, u1 = t;
#pragma unroll
            for (int d = 2; d <= 8; d++) {
                float u2 = fmaf(t2, u1, -u0);
                v[d - 1] = f32_to_tf32(u2);
                u0 = u1; u1 = u2;
            }
            uint4* dstv = (uint4*)&As[0][tid * AST + e * 8];
            dstv[0] = make_uint4(v[0], v[1], v[2], v[3]);
            dstv[1] = make_uint4(v[4], v[5], v[6], v[7]);
        }
    }

#pragma unroll 1
    for (int ib = 0; ib < INDIM / 32; ib++) {          // 32 i-blocks
#pragma unroll 1
        for (int jj = 0; jj < 8; jj++) {
            const int j = ib * 8 + jj;
            const int s = j & 1;

            // B[s] landed; A[s] produced; all warps past jj-1
            cp_wait0();
            __syncthreads();

            // prefetch B[j+1] into stage s^1
            if (j + 1 < NITER) {
                const float* src = g_Bt + (size_t)(n0 + tid) * KD2 + (j + 1) * KC;
                uint32_t dst = smem_u32(&Bs[s ^ 1][tid * BST]);
#pragma unroll
                for (int q = 0; q < 8; q++) cp_async16(dst + q * 16, src + q * 4);
            }
            cp_commit();

            // produce A[j+1] into buf s^1 (same i-block only; decoupled
            // from this jj's MMAs so it hides under the tensor burst)
            if (jj < 7) {
#pragma unroll
                for (int e = 0; e < 4; e++) {
                    float t = Ts[tid * TST + (jj + 1) * 4 + e];
                    float t2 = t + t;
                    uint32_t v[8];
                    v[0] = f32_to_tf32(t);
                    float u0 = 1.0f, u1 = t;
#pragma unroll
                    for (int d = 2; d <= 8; d++) {
                        float u2 = fmaf(t2, u1, -u0);
                        v[d - 1] = f32_to_tf32(u2);
                        u0 = u1; u1 = u2;
                    }
                    uint4* dstv = (uint4*)&As[s ^ 1][tid * AST + e * 8];
                    dstv[0] = make_uint4(v[0], v[1], v[2], v[3]);
                    dstv[1] = make_uint4(v[4], v[5], v[6], v[7]);
                }
            }

            // consume: 128 MMAs per warp (64x64 warp tile)
            const uint32_t* A_ = As[s];
            const uint32_t* B_ = Bs[s];
#pragma unroll
            for (int ks = 0; ks < 4; ks++) {
                const int kk = ks * 8;
                uint32_t a[4][4];
#pragma unroll
                for (int mf = 0; mf < 4; mf++) {
                    int r0 = warp_m * 64 + mf * 16 + gid;
                    a[mf][0] = A_[r0 * AST + kk + tg];
                    a[mf][1] = A_[(r0 + 8) * AST + kk + tg];
                    a[mf][2] = A_[r0 * AST + kk + tg + 4];
                    a[mf][3] = A_[(r0 + 8) * AST + kk + tg + 4];
                }
                uint32_t b[8][2];
#pragma unroll
                for (int nf = 0; nf < 8; nf++) {
                    int nn = warp_n * 64 + nf * 8 + gid;
                    b[nf][0] = B_[nn * BST + kk + tg];
                    b[nf][1] = B_[nn * BST + kk + tg + 4];
                }
#pragma unroll
                for (int nf = 0; nf < 8; nf++)
#pragma unroll
                    for (int mf = 0; mf < 4; mf++)
                        mma8(acc[mf][nf], a[mf], b[nf]);
            }
        }

        // ---- i-block boundary: refresh Ts, produce A[first of next ib] ----
        if (ib + 1 < INDIM / 32) {
            __syncthreads();   // all reads of Ts (and A bufs) done
            {
                const float4* src = (const float4*)(g_t + (size_t)(m0 + tid) * INDIM + (ib + 1) * 32);
                float4* dstv = (float4*)&Ts[tid * TST];
#pragma unroll
                for (int q = 0; q < 8; q++) dstv[q] = src[q];
            }
            __syncthreads();
            {
                const int nbuf = ((ib + 1) * 8) & 1;   // = 0 (ib*8 even), kept general
#pragma unroll
                for (int e = 0; e < 4; e++) {
                    float t = Ts[tid * TST + e];
                    float t2 = t + t;
                    uint32_t v[8];
                    v[0] = f32_to_tf32(t);
                    float u0 = 1.0f, u1 = t;
#pragma unroll
                    for (int d = 2; d <= 8; d++) {
                        float u2 = fmaf(t2, u1, -u0);
                        v[d - 1] = f32_to_tf32(u2);
                        u0 = u1; u1 = u2;
                    }
                    uint4* dstv = (uint4*)&As[nbuf][tid * AST + e * 8];
                    dstv[0] = make_uint4(v[0], v[1], v[2], v[3]);
                    dstv[1] = make_uint4(v[4], v[5], v[6], v[7]);
                }
            }
        }
    }

    // ---- epilogue: add T0 bias, write D ----
#pragma unroll
    for (int nf = 0; nf < 8; nf++) {
        int col = n0 + warp_n * 64 + nf * 8 + tg * 2;
        float2 bv = *(const float2*)&g_bias[col];
#pragma unroll
        for (int mf = 0; mf < 4; mf++) {
            int row = m0 + warp_m * 64 + mf * 16 + gid;
            float2* p0 = (float2*)(out + (size_t)row * OUTDIM + col);
            float2* p1 = (float2*)(out + (size_t)(row + 8) * OUTDIM + col);
            *p0 = make_float2(acc[mf][nf][0] + bv.x, acc[mf][nf][1] + bv.y);
            *p1 = make_float2(acc[mf][nf][2] + bv.x, acc[mf][nf][3] + bv.y);
        }
    }
}

// ============================ host launch ==============================
extern "C" void kernel_launch(void* const* d_in, const int* in_sizes, int n_in,
                              void* d_out, int out_size) {
    const float* x;
    const float* C;
    if (in_sizes[0] == BATCH * INDIM) { x = (const float*)d_in[0]; C = (const float*)d_in[1]; }
    else                              { x = (const float*)d_in[1]; C = (const float*)d_in[0]; }
    float* out = (float*)d_out;

    prep_t_kernel<<<(BATCH * INDIM) / (256 * 4), 256>>>(x);
    prep_Bt_kernel<<<(INDIM * OUTDIM) / 256, 256>>>(C);
    prep_bias_kernel<<<OUTDIM, 256>>>(C);

    dim3 grid(BATCH / TM, OUTDIM / TN, 1);   // 64 x 8 = 512 CTAs, 2 per SM
    cheby_gemm_kernel<<<grid, NTHREADS>>>(out);
}

// round 5
// speedup vs baseline: 1.7312x; 1.7312x over previous
#include <cuda_runtime.h>
#include <cuda_fp16.h>
#include <cstdint>

// ============================ problem sizes ============================
#define BATCH   8192
#define INDIM   1024
#define OUTDIM  1024
#define DEG1    9
#define KD2     (INDIM * 8)         // 8192 GEMM K (d=1..8; d=0 folded into bias)
#define TM      128
#define TN      128
#define KC      64                  // 8 inputs x 8 degrees per stage
#define NITER   (KD2 / KC)          // 128
#define NTH     256                 // 8 warps, warp tile 64x32

#define ASTW    36                  // A row stride in 32-bit words (64 fp16 + pad)
#define BSTW    36
#define A_WORDS (TM * ASTW)         // 4608 words = 18432 B per stage
#define B_WORDS (TN * BSTW)
#define SMEM_BYTES ((2 * A_WORDS + 3 * B_WORDS) * 4)   // 92160

#define CSCALE   64.0f
#define CINV     (1.0f / 64.0f)

// __device__ scratch (static: allocation-guard safe)
__device__ __half g_Bt[(size_t)OUTDIM * KD2];   // Bt[o][i*8+d-1] * 64, fp16
__device__ float  g_t[(size_t)BATCH * INDIM];   // clip(tanh(x))
__device__ float  g_bias[OUTDIM];               // sum_i C[i][o][0]

// ============================ helpers ==================================
__device__ __forceinline__ void cp_async16(uint32_t smem_dst, const void* gsrc) {
    asm volatile("cp.async.cg.shared.global [%0], [%1], 16;"
                 :: "r"(smem_dst), "l"(gsrc) : "memory");
}
__device__ __forceinline__ void cp_commit() {
    asm volatile("cp.async.commit_group;" ::: "memory");
}
__device__ __forceinline__ void cp_wait1() {
    asm volatile("cp.async.wait_group 1;" ::: "memory");
}
__device__ __forceinline__ uint32_t smem_u32(const void* p) {
    uint32_t a;
    asm("{ .reg .u64 t; cvta.to.shared.u64 t, %1; cvt.u32.u64 %0, t; }" : "=r"(a) : "l"(p));
    return a;
}
// mma m16n8k16 row.col f32.f16.f16.f32 (sm_80+, plain compute_103 OK)
__device__ __forceinline__ void mma16(float* c, const uint32_t* a, const uint32_t* b) {
    asm volatile(
        "mma.sync.aligned.m16n8k16.row.col.f32.f16.f16.f32 "
        "{%0,%1,%2,%3}, {%4,%5,%6,%7}, {%8,%9}, {%0,%1,%2,%3};"
        : "+f"(c[0]), "+f"(c[1]), "+f"(c[2]), "+f"(c[3])
        : "r"(a[0]), "r"(a[1]), "r"(a[2]), "r"(a[3]), "r"(b[0]), "r"(b[1]));
}

// ======================= prep: t = clip(tanh(x)) =======================
__global__ __launch_bounds__(256)
void prep_t_kernel(const float* __restrict__ x) {
    size_t i4 = (size_t)blockIdx.x * 256 + threadIdx.x;
    const float4* src = (const float4*)x;
    float4* dst = (float4*)g_t;
    float4 v = src[i4];
    float4 r;
    r.x = fminf(fmaxf(tanhf(v.x), -0.999f), 0.999f);
    r.y = fminf(fmaxf(tanhf(v.y), -0.999f), 0.999f);
    r.z = fminf(fmaxf(tanhf(v.z), -0.999f), 0.999f);
    r.w = fminf(fmaxf(tanhf(v.w), -0.999f), 0.999f);
    dst[i4] = r;
}

// ===== prep: C[i,o,d>=1] * 64 -> Bt[o, i*8+d-1]  (fp16) ================
__global__ __launch_bounds__(256)
void prep_Bt_kernel(const float* __restrict__ C) {
    int idx = blockIdx.x * 256 + threadIdx.x;   // over INDIM*OUTDIM
    int i = idx >> 10;
    int o = idx & 1023;
    const float* src = C + (size_t)i * (OUTDIM * DEG1) + (size_t)o * DEG1;
    __half* dst = g_Bt + (size_t)o * KD2 + (size_t)i * 8;
#pragma unroll
    for (int d = 1; d < DEG1; d++) dst[d - 1] = __float2half_rn(src[d] * CSCALE);
}

// ============ prep: bias[o] = sum_i C[i,o,0] (T_0 == 1) ================
__global__ __launch_bounds__(256)
void prep_bias_kernel(const float* __restrict__ C) {
    __shared__ float red[256];
    int o = blockIdx.x;
    int tid = threadIdx.x;
    float s = 0.0f;
#pragma unroll
    for (int i = tid; i < INDIM; i += 256)
        s += C[(size_t)i * (OUTDIM * DEG1) + (size_t)o * DEG1];
    red[tid] = s;
    __syncthreads();
#pragma unroll
    for (int w = 128; w > 0; w >>= 1) {
        if (tid < w) red[tid] += red[tid + w];
        __syncthreads();
    }
    if (tid == 0) g_bias[o] = red[0];
}

// ============================ main GEMM ================================
__global__ __launch_bounds__(NTH, 2)
void cheby_gemm_kernel(float* __restrict__ out) {
    extern __shared__ uint32_t sm[];
    uint32_t* const Abuf = sm;                   // 2 stages
    uint32_t* const Bbuf = sm + 2 * A_WORDS;     // 3 stages

    const int tid  = threadIdx.x;
    const int wid  = tid >> 5;
    const int lane = tid & 31;
    const int gid  = lane >> 2;
    const int tg   = lane & 3;
    const int warp_m = wid & 1;     // 2 warps along M (64 rows)
    const int warp_n = wid >> 1;    // 4 warps along N (32 cols)
    const int m0 = blockIdx.x * TM;
    const int n0 = blockIdx.y * TN;

    // producer mapping: conflict-free STS (lanes -> consecutive rows)
    const int pr = tid & 127;       // row 0..127
    const int ph = tid >> 7;        // half: 4 inputs (=32 fp16 = 64B) each

    float acc[4][4][4];
#pragma unroll
    for (int mf = 0; mf < 4; mf++)
#pragma unroll
        for (int nf = 0; nf < 4; nf++)
#pragma unroll
            for (int q = 0; q < 4; q++) acc[mf][nf][q] = 0.0f;

    const __half* browsrc = g_Bt + (size_t)(n0 + pr) * KD2 + ph * 32;
    const uint32_t bdst_base = smem_u32(Bbuf) + (uint32_t)(pr * BSTW + ph * 16) * 4u;

    // ---- prologue: B[0] -> buf0 (G0), B[1] -> buf1 (G1) ----
#pragma unroll
    for (int q = 0; q < 4; q++) cp_async16(bdst_base + q * 16, browsrc + q * 8);
    cp_commit();
#pragma unroll
    for (int q = 0; q < 4; q++)
        cp_async16(bdst_base + B_WORDS * 4 + q * 16, browsrc + KC + q * 8);
    cp_commit();

    const float4* tsrc = (const float4*)(g_t + (size_t)(m0 + pr) * INDIM + ph * 4);
    // t for jj=0, produce A[0] into stage 0
    float4 tv = tsrc[0];
    {
        uint32_t* dst = Abuf + pr * ASTW + ph * 16;
#pragma unroll
        for (int e = 0; e < 4; e++) {
            float t = (&tv.x)[e];
            float t2 = t + t;
            float v[8];
            v[0] = t;
            float u0 = 1.0f, u1 = t;
#pragma unroll
            for (int d = 2; d <= 8; d++) {
                float u2 = fmaf(t2, u1, -u0);
                v[d - 1] = u2;
                u0 = u1; u1 = u2;
            }
            uint4 pk;
            pk.x = __half2_raw(__floats2half2_rn(v[0], v[1])).x | ((uint32_t)__half2_raw(__floats2half2_rn(v[0], v[1])).y << 16);
            // use direct reinterpret instead:
            __half2 h0 = __floats2half2_rn(v[0], v[1]);
            __half2 h1 = __floats2half2_rn(v[2], v[3]);
            __half2 h2 = __floats2half2_rn(v[4], v[5]);
            __half2 h3 = __floats2half2_rn(v[6], v[7]);
            pk.x = *(uint32_t*)&h0; pk.y = *(uint32_t*)&h1;
            pk.z = *(uint32_t*)&h2; pk.w = *(uint32_t*)&h3;
            *(uint4*)(dst + e * 4) = pk;
        }
    }
    // prefetch t for jj=1
    float4 tn = tsrc[2];   // jj*8 floats per jj => float4 index jj*2

    int bb = 0;            // B ring buffer index = jj % 3

#pragma unroll 1
    for (int jj = 0; jj < NITER; jj++) {
        const int s = jj & 1;

        // B[jj] complete (only G[jj+1] may be outstanding); A[jj] produced
        cp_wait1();
        __syncthreads();

        // ---- issue B[jj+2] into ring slot (bb+2)%3 (free since jj-1) ----
        {
            int bb2 = bb + 2; if (bb2 >= 3) bb2 -= 3;
            if (jj + 2 < NITER) {
                const __half* src = browsrc + (jj + 2) * KC;
                uint32_t dst = bdst_base + (uint32_t)(bb2 * B_WORDS) * 4u;
#pragma unroll
                for (int q = 0; q < 4; q++) cp_async16(dst + q * 16, src + q * 8);
            }
            cp_commit();   // keep group counting aligned (empty group OK)
        }

        // ---- produce A[jj+1] into stage s^1; prefetch t for jj+2 ----
        if (jj + 1 < NITER) {
            uint32_t* dst = Abuf + (s ^ 1) * A_WORDS + pr * ASTW + ph * 16;
#pragma unroll
            for (int e = 0; e < 4; e++) {
                float t = (&tn.x)[e];
                float t2 = t + t;
                float v[8];
                v[0] = t;
                float u0 = 1.0f, u1 = t;
#pragma unroll
                for (int d = 2; d <= 8; d++) {
                    float u2 = fmaf(t2, u1, -u0);
                    v[d - 1] = u2;
                    u0 = u1; u1 = u2;
                }
                __half2 h0 = __floats2half2_rn(v[0], v[1]);
                __half2 h1 = __floats2half2_rn(v[2], v[3]);
                __half2 h2 = __floats2half2_rn(v[4], v[5]);
                __half2 h3 = __floats2half2_rn(v[6], v[7]);
                uint4 pk;
                pk.x = *(uint32_t*)&h0; pk.y = *(uint32_t*)&h1;
                pk.z = *(uint32_t*)&h2; pk.w = *(uint32_t*)&h3;
                *(uint4*)(dst + e * 4) = pk;
            }
            if (jj + 2 < NITER) tn = tsrc[(jj + 2) * 2];
        }

        // ---- consume: 64 MMAs per warp (4 k-chunks of 16) ----
        const uint32_t* A_ = Abuf + s * A_WORDS;
        const uint32_t* B_ = Bbuf + bb * B_WORDS;
#pragma unroll
        for (int kc = 0; kc < 4; kc++) {
            const int ko = kc * 8;   // words
            uint32_t a[4][4];
#pragma unroll
            for (int mf = 0; mf < 4; mf++) {
                int base = (warp_m * 64 + mf * 16 + gid) * ASTW + ko + tg;
                a[mf][0] = A_[base];
                a[mf][1] = A_[base + 8 * ASTW];
                a[mf][2] = A_[base + 4];
                a[mf][3] = A_[base + 8 * ASTW + 4];
            }
            uint32_t b[4][2];
#pragma unroll
            for (int nf = 0; nf < 4; nf++) {
                int base = (warp_n * 32 + nf * 8 + gid) * BSTW + ko + tg;
                b[nf][0] = B_[base];
                b[nf][1] = B_[base + 4];
            }
#pragma unroll
            for (int nf = 0; nf < 4; nf++)
#pragma unroll
                for (int mf = 0; mf < 4; mf++)
                    mma16(acc[mf][nf], a[mf], b[nf]);
        }

        bb = (bb == 2) ? 0 : bb + 1;
    }

    // ---- epilogue: unscale, add T0 bias, write D ----
#pragma unroll
    for (int nf = 0; nf < 4; nf++) {
        int col = n0 + warp_n * 32 + nf * 8 + tg * 2;
        float2 bv = *(const float2*)&g_bias[col];
#pragma unroll
        for (int mf = 0; mf < 4; mf++) {
            int row = m0 + warp_m * 64 + mf * 16 + gid;
            float2* p0 = (float2*)(out + (size_t)row * OUTDIM + col);
            float2* p1 = (float2*)(out + (size_t)(row + 8) * OUTDIM + col);
            *p0 = make_float2(fmaf(acc[mf][nf][0], CINV, bv.x),
                              fmaf(acc[mf][nf][1], CINV, bv.y));
            *p1 = make_float2(fmaf(acc[mf][nf][2], CINV, bv.x),
                              fmaf(acc[mf][nf][3], CINV, bv.y));
        }
    }
}

// ============================ host launch ==============================
extern "C" void kernel_launch(void* const* d_in, const int* in_sizes, int n_in,
                              void* d_out, int out_size) {
    const float* x;
    const float* C;
    if (in_sizes[0] == BATCH * INDIM) { x = (const float*)d_in[0]; C = (const float*)d_in[1]; }
    else                              { x = (const float*)d_in[1]; C = (const float*)d_in[0]; }
    float* out = (float*)d_out;

    prep_t_kernel<<<(BATCH * INDIM) / (256 * 4), 256>>>(x);
    prep_Bt_kernel<<<(INDIM * OUTDIM) / 256, 256>>>(C);
    prep_bias_kernel<<<OUTDIM, 256>>>(C);

    static int smem_set = 0;
    if (!smem_set) {
        cudaFuncSetAttribute(cheby_gemm_kernel,
                             cudaFuncAttributeMaxDynamicSharedMemorySize, SMEM_BYTES);
        smem_set = 1;
    }
    dim3 grid(BATCH / TM, OUTDIM / TN, 1);   // 64 x 8 = 512 CTAs, 2/SM
    cheby_gemm_kernel<<<grid, NTH, SMEM_BYTES>>>(out);
}

// round 6
// speedup vs baseline: 1.8569x; 1.0726x over previous
#include <cuda_runtime.h>
#include <cuda_fp16.h>
#include <cstdint>

// ============================ problem sizes ============================
#define BATCH   8192
#define INDIM   1024
#define OUTDIM  1024
#define DEG1    9
#define KD2     (INDIM * 8)         // 8192 GEMM K (d=1..8; d=0 folded into bias)
#define TM      128
#define TN      128
#define KC      64                  // 8 inputs x 8 degrees per stage
#define NITER   (KD2 / KC)          // 128
#define NTH     256                 // 8 warps, warp tile 64x32

#define ASTW    36                  // A row stride in 32-bit words (64 fp16 + pad)
#define BSTW    36
#define ROWB    144                 // row stride in bytes
#define A_WORDS (TM * ASTW)         // 4608 words = 18432 B per stage
#define B_WORDS (TN * BSTW)
#define A_BYTES (A_WORDS * 4)
#define B_BYTES (B_WORDS * 4)
#define SMEM_BYTES ((2 * A_WORDS + 3 * B_WORDS) * 4)   // 92160

#define CSCALE   64.0f
#define CINV     (1.0f / 64.0f)

// __device__ scratch (static: allocation-guard safe)
__device__ __half g_Bt[(size_t)OUTDIM * KD2];   // Bt[o][i*8+d-1] * 64, fp16
__device__ float  g_t[(size_t)BATCH * INDIM];   // clip(tanh(x))
__device__ float  g_bias[OUTDIM];               // sum_i C[i][o][0]

// ============================ helpers ==================================
__device__ __forceinline__ void cp_async16(uint32_t smem_dst, const void* gsrc) {
    asm volatile("cp.async.cg.shared.global [%0], [%1], 16;"
                 :: "r"(smem_dst), "l"(gsrc) : "memory");
}
__device__ __forceinline__ void cp_commit() {
    asm volatile("cp.async.commit_group;" ::: "memory");
}
__device__ __forceinline__ void cp_wait1() {
    asm volatile("cp.async.wait_group 1;" ::: "memory");
}
__device__ __forceinline__ uint32_t smem_u32(const void* p) {
    uint32_t a;
    asm("{ .reg .u64 t; cvta.to.shared.u64 t, %1; cvt.u32.u64 %0, t; }" : "=r"(a) : "l"(p));
    return a;
}
// mma m16n8k16 row.col f32.f16.f16.f32 (sm_80+, plain compute_103 OK)
__device__ __forceinline__ void mma16(float* c, const uint32_t* a, uint32_t b0, uint32_t b1) {
    asm volatile(
        "mma.sync.aligned.m16n8k16.row.col.f32.f16.f16.f32 "
        "{%0,%1,%2,%3}, {%4,%5,%6,%7}, {%8,%9}, {%0,%1,%2,%3};"
        : "+f"(c[0]), "+f"(c[1]), "+f"(c[2]), "+f"(c[3])
        : "r"(a[0]), "r"(a[1]), "r"(a[2]), "r"(a[3]), "r"(b0), "r"(b1));
}
// ldmatrix x4 (sm_75+)
__device__ __forceinline__ void ldm4(uint32_t* r, uint32_t addr) {
    asm volatile("ldmatrix.sync.aligned.m8n8.x4.shared.b16 {%0,%1,%2,%3}, [%4];"
                 : "=r"(r[0]), "=r"(r[1]), "=r"(r[2]), "=r"(r[3]) : "r"(addr));
}

// ======================= prep: t = clip(tanh(x)) =======================
__global__ __launch_bounds__(256)
void prep_t_kernel(const float* __restrict__ x) {
    size_t i4 = (size_t)blockIdx.x * 256 + threadIdx.x;
    const float4* src = (const float4*)x;
    float4* dst = (float4*)g_t;
    float4 v = src[i4];
    float4 r;
    r.x = fminf(fmaxf(tanhf(v.x), -0.999f), 0.999f);
    r.y = fminf(fmaxf(tanhf(v.y), -0.999f), 0.999f);
    r.z = fminf(fmaxf(tanhf(v.z), -0.999f), 0.999f);
    r.w = fminf(fmaxf(tanhf(v.w), -0.999f), 0.999f);
    dst[i4] = r;
}

// ===== prep: C[i,o,d>=1] * 64 -> Bt[o, i*8+d-1]  (fp16) ================
__global__ __launch_bounds__(256)
void prep_Bt_kernel(const float* __restrict__ C) {
    int idx = blockIdx.x * 256 + threadIdx.x;   // over INDIM*OUTDIM
    int i = idx >> 10;
    int o = idx & 1023;
    const float* src = C + (size_t)i * (OUTDIM * DEG1) + (size_t)o * DEG1;
    __half* dst = g_Bt + (size_t)o * KD2 + (size_t)i * 8;
#pragma unroll
    for (int d = 1; d < DEG1; d++) dst[d - 1] = __float2half_rn(src[d] * CSCALE);
}

// ============ prep: bias[o] = sum_i C[i,o,0] (T_0 == 1) ================
__global__ __launch_bounds__(256)
void prep_bias_kernel(const float* __restrict__ C) {
    __shared__ float red[256];
    int o = blockIdx.x;
    int tid = threadIdx.x;
    float s = 0.0f;
#pragma unroll
    for (int i = tid; i < INDIM; i += 256)
        s += C[(size_t)i * (OUTDIM * DEG1) + (size_t)o * DEG1];
    red[tid] = s;
    __syncthreads();
#pragma unroll
    for (int w = 128; w > 0; w >>= 1) {
        if (tid < w) red[tid] += red[tid + w];
        __syncthreads();
    }
    if (tid == 0) g_bias[o] = red[0];
}

// ============================ main GEMM ================================
__global__ __launch_bounds__(NTH, 2)
void cheby_gemm_kernel(float* __restrict__ out) {
    extern __shared__ uint32_t sm[];
    uint32_t* const Abuf = sm;                   // 2 stages
    uint32_t* const Bbuf = sm + 2 * A_WORDS;     // 3 stages

    const int tid  = threadIdx.x;
    const int wid  = tid >> 5;
    const int lane = tid & 31;
    const int gid  = lane >> 2;
    const int tg   = lane & 3;
    const int warp_m = wid & 1;     // 2 warps along M (64 rows)
    const int warp_n = wid >> 1;    // 4 warps along N (32 cols)
    const int m0 = blockIdx.x * TM;
    const int n0 = blockIdx.y * TN;

    // producer mapping: conflict-free STS (lanes -> consecutive rows)
    const int pr = tid & 127;       // row 0..127
    const int ph = tid >> 7;        // half: 4 inputs (=32 fp16 = 64B) each

    float acc[4][4][4];
#pragma unroll
    for (int mf = 0; mf < 4; mf++)
#pragma unroll
        for (int nf = 0; nf < 4; nf++)
#pragma unroll
            for (int q = 0; q < 4; q++) acc[mf][nf][q] = 0.0f;

    const __half* browsrc = g_Bt + (size_t)(n0 + pr) * KD2 + ph * 32;
    const uint32_t bdst_base = smem_u32(Bbuf) + (uint32_t)(pr * BSTW + ph * 16) * 4u;

    // ldmatrix per-lane base addresses
    // A: row = warp_m*64 + (lane&7) + ((lane>>3)&1)*8  (+ mf*16), kbyte = (lane>>4)*16 (+ kc*32)
    const uint32_t a_ldm_base = smem_u32(Abuf)
        + (uint32_t)(warp_m * 64 + (lane & 7) + ((lane >> 3) & 1) * 8) * ROWB
        + (uint32_t)((lane >> 4) * 16);
    // B: row = warp_n*32 + (lane&7) + (lane>>4)*8  (+ p*16), kbyte = ((lane>>3)&1)*16 (+ kc*32)
    const uint32_t b_ldm_base = smem_u32(Bbuf)
        + (uint32_t)(warp_n * 32 + (lane & 7) + (lane >> 4) * 8) * ROWB
        + (uint32_t)(((lane >> 3) & 1) * 16);

    // ---- prologue: B[0] -> slot0 (G0), B[1] -> slot1 (G1) ----
#pragma unroll
    for (int q = 0; q < 4; q++) cp_async16(bdst_base + q * 16, browsrc + q * 8);
    cp_commit();
#pragma unroll
    for (int q = 0; q < 4; q++)
        cp_async16(bdst_base + B_BYTES + q * 16, browsrc + KC + q * 8);
    cp_commit();

    const float4* tsrc = (const float4*)(g_t + (size_t)(m0 + pr) * INDIM + ph * 4);
    // t for jj=0, produce A[0] into stage 0
    float4 tv = tsrc[0];
    {
        uint32_t* dst = Abuf + pr * ASTW + ph * 16;
#pragma unroll
        for (int e = 0; e < 4; e++) {
            float t = (&tv.x)[e];
            float t2 = t + t;
            float v[8];
            v[0] = t;
            float u0 = 1.0f, u1 = t;
#pragma unroll
            for (int d = 2; d <= 8; d++) {
                float u2 = fmaf(t2, u1, -u0);
                v[d - 1] = u2;
                u0 = u1; u1 = u2;
            }
            __half2 h0 = __floats2half2_rn(v[0], v[1]);
            __half2 h1 = __floats2half2_rn(v[2], v[3]);
            __half2 h2 = __floats2half2_rn(v[4], v[5]);
            __half2 h3 = __floats2half2_rn(v[6], v[7]);
            uint4 pk;
            pk.x = *(uint32_t*)&h0; pk.y = *(uint32_t*)&h1;
            pk.z = *(uint32_t*)&h2; pk.w = *(uint32_t*)&h3;
            *(uint4*)(dst + e * 4) = pk;
        }
    }
    // prefetch t for jj=1
    float4 tn = tsrc[2];

    int bb = 0;            // B ring slot = jj % 3

#pragma unroll 1
    for (int jj = 0; jj < NITER; jj++) {
        const int s = jj & 1;

        // B[jj] complete (only B[jj+1]'s group may be outstanding); A[jj] produced
        cp_wait1();
        __syncthreads();

        // ---- issue B[jj+2] into ring slot (bb+2)%3 ----
        {
            int bb2 = bb + 2; if (bb2 >= 3) bb2 -= 3;
            if (jj + 2 < NITER) {
                const __half* src = browsrc + (jj + 2) * KC;
                uint32_t dst = bdst_base + (uint32_t)(bb2 * B_BYTES);
#pragma unroll
                for (int q = 0; q < 4; q++) cp_async16(dst + q * 16, src + q * 8);
            }
            cp_commit();   // empty group near tail keeps counting aligned
        }

        // ---- produce A[jj+1] into stage s^1; prefetch t for jj+2 ----
        if (jj + 1 < NITER) {
            uint32_t* dst = Abuf + (s ^ 1) * A_WORDS + pr * ASTW + ph * 16;
#pragma unroll
            for (int e = 0; e < 4; e++) {
                float t = (&tn.x)[e];
                float t2 = t + t;
                float v[8];
                v[0] = t;
                float u0 = 1.0f, u1 = t;
#pragma unroll
                for (int d = 2; d <= 8; d++) {
                    float u2 = fmaf(t2, u1, -u0);
                    v[d - 1] = u2;
                    u0 = u1; u1 = u2;
                }
                __half2 h0 = __floats2half2_rn(v[0], v[1]);
                __half2 h1 = __floats2half2_rn(v[2], v[3]);
                __half2 h2 = __floats2half2_rn(v[4], v[5]);
                __half2 h3 = __floats2half2_rn(v[6], v[7]);
                uint4 pk;
                pk.x = *(uint32_t*)&h0; pk.y = *(uint32_t*)&h1;
                pk.z = *(uint32_t*)&h2; pk.w = *(uint32_t*)&h3;
                *(uint4*)(dst + e * 4) = pk;
            }
            if (jj + 2 < NITER) tn = tsrc[(jj + 2) * 2];
        }

        // ---- consume: 64 MMAs per warp, ldmatrix fragment loads ----
        const uint32_t a_addr0 = a_ldm_base + (uint32_t)(s * A_BYTES);
        const uint32_t b_addr0 = b_ldm_base + (uint32_t)(bb * B_BYTES);
#pragma unroll
        for (int kc = 0; kc < 4; kc++) {
            const uint32_t kb = kc * 32;
            uint32_t a[4][4];
#pragma unroll
            for (int mf = 0; mf < 4; mf++)
                ldm4(a[mf], a_addr0 + (uint32_t)(mf * 16 * ROWB) + kb);
            uint32_t b[2][4];   // b[p] = {nf=2p klo, khi, nf=2p+1 klo, khi}
#pragma unroll
            for (int p = 0; p < 2; p++)
                ldm4(b[p], b_addr0 + (uint32_t)(p * 16 * ROWB) + kb);
#pragma unroll
            for (int p = 0; p < 2; p++) {
#pragma unroll
                for (int mf = 0; mf < 4; mf++) {
                    mma16(acc[mf][2 * p],     a[mf], b[p][0], b[p][1]);
                    mma16(acc[mf][2 * p + 1], a[mf], b[p][2], b[p][3]);
                }
            }
        }

        bb = (bb == 2) ? 0 : bb + 1;
    }

    // ---- epilogue: unscale, add T0 bias, write D ----
#pragma unroll
    for (int nf = 0; nf < 4; nf++) {
        int col = n0 + warp_n * 32 + nf * 8 + tg * 2;
        float2 bv = *(const float2*)&g_bias[col];
#pragma unroll
        for (int mf = 0; mf < 4; mf++) {
            int row = m0 + warp_m * 64 + mf * 16 + gid;
            float2* p0 = (float2*)(out + (size_t)row * OUTDIM + col);
            float2* p1 = (float2*)(out + (size_t)(row + 8) * OUTDIM + col);
            *p0 = make_float2(fmaf(acc[mf][nf][0], CINV, bv.x),
                              fmaf(acc[mf][nf][1], CINV, bv.y));
            *p1 = make_float2(fmaf(acc[mf][nf][2], CINV, bv.x),
                              fmaf(acc[mf][nf][3], CINV, bv.y));
        }
    }
}

// ============================ host launch ==============================
extern "C" void kernel_launch(void* const* d_in, const int* in_sizes, int n_in,
                              void* d_out, int out_size) {
    const float* x;
    const float* C;
    if (in_sizes[0] == BATCH * INDIM) { x = (const float*)d_in[0]; C = (const float*)d_in[1]; }
    else                              { x = (const float*)d_in[1]; C = (const float*)d_in[0]; }
    float* out = (float*)d_out;

    prep_t_kernel<<<(BATCH * INDIM) / (256 * 4), 256>>>(x);
    prep_Bt_kernel<<<(INDIM * OUTDIM) / 256, 256>>>(C);
    prep_bias_kernel<<<OUTDIM, 256>>>(C);

    static int smem_set = 0;
    if (!smem_set) {
        cudaFuncSetAttribute(cheby_gemm_kernel,
                             cudaFuncAttributeMaxDynamicSharedMemorySize, SMEM_BYTES);
        smem_set = 1;
    }
    dim3 grid(BATCH / TM, OUTDIM / TN, 1);   // 64 x 8 = 512 CTAs, 2/SM
    cheby_gemm_kernel<<<grid, NTH, SMEM_BYTES>>>(out);
}

// round 7
// speedup vs baseline: 2.1704x; 1.1688x over previous
#include <cuda_runtime.h>
#include <cuda_fp16.h>
#include <cstdint>

// ============================ problem sizes ============================
#define BATCH   8192
#define INDIM   1024
#define OUTDIM  1024
#define DEG1    9
#define KD2     (INDIM * 8)         // 8192 GEMM K (d=1..8; d=0 folded into bias)
#define TM      128
#define TN      128
#define KC      64                  // 8 inputs x 8 degrees per stage
#define NITER   (KD2 / KC)          // 128
#define NTH     256                 // 8 warps, warp tile 64x32

#define ASTW    36                  // A row stride in 32-bit words (64 fp16 + pad)
#define BSTW    36
#define ROWB    144                 // row stride in bytes
#define A_WORDS (TM * ASTW)         // 4608 words = 18432 B per stage
#define B_WORDS (TN * BSTW)
#define A_BYTES (A_WORDS * 4)
#define B_BYTES (B_WORDS * 4)
#define SMEM_BYTES ((2 * A_WORDS + 3 * B_WORDS) * 4)   // 92160

#define CSCALE   64.0f
#define CINV     (1.0f / 64.0f)

// __device__ scratch (static: allocation-guard safe)
__device__ __half g_Bt[(size_t)OUTDIM * KD2];   // Bt[o][i*8+d-1] * 64, fp16
__device__ float  g_t[(size_t)BATCH * INDIM];   // clip(tanh(x))
__device__ float  g_bias[OUTDIM];               // sum_i C[i][o][0]

// ============================ helpers ==================================
__device__ __forceinline__ void cp_async16(uint32_t smem_dst, const void* gsrc) {
    asm volatile("cp.async.cg.shared.global [%0], [%1], 16;"
                 :: "r"(smem_dst), "l"(gsrc) : "memory");
}
__device__ __forceinline__ void cp_commit() {
    asm volatile("cp.async.commit_group;" ::: "memory");
}
__device__ __forceinline__ void cp_wait1() {
    asm volatile("cp.async.wait_group 1;" ::: "memory");
}
__device__ __forceinline__ uint32_t smem_u32(const void* p) {
    uint32_t a;
    asm("{ .reg .u64 t; cvta.to.shared.u64 t, %1; cvt.u32.u64 %0, t; }" : "=r"(a) : "l"(p));
    return a;
}
// mma m16n8k16 row.col f32.f16.f16.f32 (sm_80+, plain compute_103 OK)
__device__ __forceinline__ void mma16(float* c, const uint32_t* a, uint32_t b0, uint32_t b1) {
    asm volatile(
        "mma.sync.aligned.m16n8k16.row.col.f32.f16.f16.f32 "
        "{%0,%1,%2,%3}, {%4,%5,%6,%7}, {%8,%9}, {%0,%1,%2,%3};"
        : "+f"(c[0]), "+f"(c[1]), "+f"(c[2]), "+f"(c[3])
        : "r"(a[0]), "r"(a[1]), "r"(a[2]), "r"(a[3]), "r"(b0), "r"(b1));
}
// ldmatrix x4 (sm_75+)
__device__ __forceinline__ void ldm4(uint32_t* r, uint32_t addr) {
    asm volatile("ldmatrix.sync.aligned.m8n8.x4.shared.b16 {%0,%1,%2,%3}, [%4];"
                 : "=r"(r[0]), "=r"(r[1]), "=r"(r[2]), "=r"(r[3]) : "r"(addr));
}

// ============ prep 1: t = clip(tanh(x)); blocks 0-3 zero g_bias ========
__global__ __launch_bounds__(256)
void prep_t_kernel(const float* __restrict__ x) {
    if (blockIdx.x < 4) g_bias[blockIdx.x * 256 + threadIdx.x] = 0.0f;
    size_t i4 = (size_t)blockIdx.x * 256 + threadIdx.x;
    const float4* src = (const float4*)x;
    float4* dst = (float4*)g_t;
    float4 v = src[i4];
    float4 r;
    r.x = fminf(fmaxf(tanhf(v.x), -0.999f), 0.999f);
    r.y = fminf(fmaxf(tanhf(v.y), -0.999f), 0.999f);
    r.z = fminf(fmaxf(tanhf(v.z), -0.999f), 0.999f);
    r.w = fminf(fmaxf(tanhf(v.w), -0.999f), 0.999f);
    dst[i4] = r;
}

// ==== prep 2: C[i,o,d>=1]*64 -> Bt[o, i*8+d-1]; d=0 -> atomic bias =====
__global__ __launch_bounds__(256)
void prep_Bt_kernel(const float* __restrict__ C) {
    int idx = blockIdx.x * 256 + threadIdx.x;   // over INDIM*OUTDIM
    int i = idx >> 10;
    int o = idx & 1023;
    const float* src = C + (size_t)i * (OUTDIM * DEG1) + (size_t)o * DEG1;
    __half* dst = g_Bt + (size_t)o * KD2 + (size_t)i * 8;
#pragma unroll
    for (int d = 1; d < DEG1; d++) dst[d - 1] = __float2half_rn(src[d] * CSCALE);
    atomicAdd(&g_bias[o], src[0]);              // T_0 == 1 contribution
}

// ============================ main GEMM ================================
__global__ __launch_bounds__(NTH, 2)
void cheby_gemm_kernel(float* __restrict__ out) {
    extern __shared__ uint32_t sm[];
    uint32_t* const Abuf = sm;                   // 2 stages
    uint32_t* const Bbuf = sm + 2 * A_WORDS;     // 3 stages

    const int tid  = threadIdx.x;
    const int wid  = tid >> 5;
    const int lane = tid & 31;
    const int gid  = lane >> 2;
    const int tg   = lane & 3;
    const int warp_m = wid & 1;     // 2 warps along M (64 rows)
    const int warp_n = wid >> 1;    // 4 warps along N (32 cols)
    const int m0 = blockIdx.x * TM;
    const int n0 = blockIdx.y * TN;

    // producer mapping: conflict-free STS (lanes -> consecutive rows)
    const int pr = tid & 127;       // row 0..127
    const int ph = tid >> 7;        // half: 4 inputs (=32 fp16 = 64B) each

    float acc[4][4][4];
#pragma unroll
    for (int mf = 0; mf < 4; mf++)
#pragma unroll
        for (int nf = 0; nf < 4; nf++)
#pragma unroll
            for (int q = 0; q < 4; q++) acc[mf][nf][q] = 0.0f;

    const __half* browsrc = g_Bt + (size_t)(n0 + pr) * KD2 + ph * 32;
    const uint32_t bdst_base = smem_u32(Bbuf) + (uint32_t)(pr * BSTW + ph * 16) * 4u;

    // ldmatrix per-lane base addresses
    const uint32_t a_ldm_base = smem_u32(Abuf)
        + (uint32_t)(warp_m * 64 + (lane & 7) + ((lane >> 3) & 1) * 8) * ROWB
        + (uint32_t)((lane >> 4) * 16);
    const uint32_t b_ldm_base = smem_u32(Bbuf)
        + (uint32_t)(warp_n * 32 + (lane & 7) + (lane >> 4) * 8) * ROWB
        + (uint32_t)(((lane >> 3) & 1) * 16);

    // ---- prologue: B[0] -> slot0 (G0), B[1] -> slot1 (G1) ----
#pragma unroll
    for (int q = 0; q < 4; q++) cp_async16(bdst_base + q * 16, browsrc + q * 8);
    cp_commit();
#pragma unroll
    for (int q = 0; q < 4; q++)
        cp_async16(bdst_base + B_BYTES + q * 16, browsrc + KC + q * 8);
    cp_commit();

    const float4* tsrc = (const float4*)(g_t + (size_t)(m0 + pr) * INDIM + ph * 4);
    // t for jj=0, produce A[0] into stage 0
    float4 tv = tsrc[0];
    {
        uint32_t* dst = Abuf + pr * ASTW + ph * 16;
#pragma unroll
        for (int e = 0; e < 4; e++) {
            float t = (&tv.x)[e];
            float t2 = t + t;
            float v[8];
            v[0] = t;
            float u0 = 1.0f, u1 = t;
#pragma unroll
            for (int d = 2; d <= 8; d++) {
                float u2 = fmaf(t2, u1, -u0);
                v[d - 1] = u2;
                u0 = u1; u1 = u2;
            }
            __half2 h0 = __floats2half2_rn(v[0], v[1]);
            __half2 h1 = __floats2half2_rn(v[2], v[3]);
            __half2 h2 = __floats2half2_rn(v[4], v[5]);
            __half2 h3 = __floats2half2_rn(v[6], v[7]);
            uint4 pk;
            pk.x = *(uint32_t*)&h0; pk.y = *(uint32_t*)&h1;
            pk.z = *(uint32_t*)&h2; pk.w = *(uint32_t*)&h3;
            *(uint4*)(dst + e * 4) = pk;
        }
    }
    // prefetch t for jj=1
    float4 tn = tsrc[2];

    int bb = 0;            // B ring slot = jj % 3

#pragma unroll 1
    for (int jj = 0; jj < NITER; jj++) {
        const int s = jj & 1;

        // B[jj] complete (only B[jj+1]'s group outstanding); A[jj] produced
        cp_wait1();
        __syncthreads();

        // ---- TENSOR FIRST: ldmatrix + 64 MMAs, engage the pipe now ----
        const uint32_t a_addr0 = a_ldm_base + (uint32_t)(s * A_BYTES);
        const uint32_t b_addr0 = b_ldm_base + (uint32_t)(bb * B_BYTES);
#pragma unroll
        for (int kc = 0; kc < 4; kc++) {
            const uint32_t kb = kc * 32;
            uint32_t a[4][4];
#pragma unroll
            for (int mf = 0; mf < 4; mf++)
                ldm4(a[mf], a_addr0 + (uint32_t)(mf * 16 * ROWB) + kb);
            uint32_t b[2][4];   // b[p] = {nf=2p klo, khi, nf=2p+1 klo, khi}
#pragma unroll
            for (int p = 0; p < 2; p++)
                ldm4(b[p], b_addr0 + (uint32_t)(p * 16 * ROWB) + kb);
#pragma unroll
            for (int p = 0; p < 2; p++) {
#pragma unroll
                for (int mf = 0; mf < 4; mf++) {
                    mma16(acc[mf][2 * p],     a[mf], b[p][0], b[p][1]);
                    mma16(acc[mf][2 * p + 1], a[mf], b[p][2], b[p][3]);
                }
            }
        }

        // ---- async B[jj+2] into ring slot (bb+2)%3 (needed 2 jj later) ----
        {
            int bb2 = bb + 2; if (bb2 >= 3) bb2 -= 3;
            if (jj + 2 < NITER) {
                const __half* src = browsrc + (jj + 2) * KC;
                uint32_t dst = bdst_base + (uint32_t)(bb2 * B_BYTES);
#pragma unroll
                for (int q = 0; q < 4; q++) cp_async16(dst + q * 16, src + q * 8);
            }
            cp_commit();   // empty group near tail keeps counting aligned
        }

        // ---- produce A[jj+1] under the tensor shadow; prefetch t[jj+2] ----
        if (jj + 1 < NITER) {
            uint32_t* dst = Abuf + (s ^ 1) * A_WORDS + pr * ASTW + ph * 16;
#pragma unroll
            for (int e = 0; e < 4; e++) {
                float t = (&tn.x)[e];
                float t2 = t + t;
                float v[8];
                v[0] = t;
                float u0 = 1.0f, u1 = t;
#pragma unroll
                for (int d = 2; d <= 8; d++) {
                    float u2 = fmaf(t2, u1, -u0);
                    v[d - 1] = u2;
                    u0 = u1; u1 = u2;
                }
                __half2 h0 = __floats2half2_rn(v[0], v[1]);
                __half2 h1 = __floats2half2_rn(v[2], v[3]);
                __half2 h2 = __floats2half2_rn(v[4], v[5]);
                __half2 h3 = __floats2half2_rn(v[6], v[7]);
                uint4 pk;
                pk.x = *(uint32_t*)&h0; pk.y = *(uint32_t*)&h1;
                pk.z = *(uint32_t*)&h2; pk.w = *(uint32_t*)&h3;
                *(uint4*)(dst + e * 4) = pk;
            }
            if (jj + 2 < NITER) tn = tsrc[(jj + 2) * 2];
        }

        bb = (bb == 2) ? 0 : bb + 1;
    }

    // ---- epilogue: unscale, add T0 bias, write D ----
#pragma unroll
    for (int nf = 0; nf < 4; nf++) {
        int col = n0 + warp_n * 32 + nf * 8 + tg * 2;
        float2 bv = *(const float2*)&g_bias[col];
#pragma unroll
        for (int mf = 0; mf < 4; mf++) {
            int row = m0 + warp_m * 64 + mf * 16 + gid;
            float2* p0 = (float2*)(out + (size_t)row * OUTDIM + col);
            float2* p1 = (float2*)(out + (size_t)(row + 8) * OUTDIM + col);
            *p0 = make_float2(fmaf(acc[mf][nf][0], CINV, bv.x),
                              fmaf(acc[mf][nf][1], CINV, bv.y));
            *p1 = make_float2(fmaf(acc[mf][nf][2], CINV, bv.x),
                              fmaf(acc[mf][nf][3], CINV, bv.y));
        }
    }
}

// ============================ host launch ==============================
extern "C" void kernel_launch(void* const* d_in, const int* in_sizes, int n_in,
                              void* d_out, int out_size) {
    const float* x;
    const float* C;
    if (in_sizes[0] == BATCH * INDIM) { x = (const float*)d_in[0]; C = (const float*)d_in[1]; }
    else                              { x = (const float*)d_in[1]; C = (const float*)d_in[0]; }
    float* out = (float*)d_out;

    prep_t_kernel<<<(BATCH * INDIM) / (256 * 4), 256>>>(x);
    prep_Bt_kernel<<<(INDIM * OUTDIM) / 256, 256>>>(C);

    static int smem_set = 0;
    if (!smem_set) {
        cudaFuncSetAttribute(cheby_gemm_kernel,
                             cudaFuncAttributeMaxDynamicSharedMemorySize, SMEM_BYTES);
        smem_set = 1;
    }
    dim3 grid(BATCH / TM, OUTDIM / TN, 1);   // 64 x 8 = 512 CTAs, 2/SM
    cheby_gemm_kernel<<<grid, NTH, SMEM_BYTES>>>(out);
}

// round 8
// speedup vs baseline: 2.2951x; 1.0575x over previous
#include <cuda_runtime.h>
#include <cuda_fp16.h>
#include <cstdint>

// ============================ problem sizes ============================
#define BATCH   8192
#define INDIM   1024
#define OUTDIM  1024
#define DEG1    9
#define KD2     (INDIM * 8)         // 8192 GEMM K (d=1..8; d=0 folded into bias)
#define TM      128
#define TN      128
#define KC      64                  // 8 inputs x 8 degrees per stage
#define NITER   (KD2 / KC)          // 128
#define NTH     256                 // 8 warps, warp tile 64x32

#define ASTW    36                  // A row stride in 32-bit words
#define BSTW    36
#define ROWB    144                 // row stride in bytes
#define A_WORDS (TM * ASTW)         // 4608 words = 18432 B per stage
#define B_WORDS (TN * BSTW)
#define A_BYTES (A_WORDS * 4)
#define B_BYTES (B_WORDS * 4)
#define MBW     16                  // 64 B header for 6 mbarriers
#define SMEM_BYTES ((MBW + 2 * A_WORDS + 3 * B_WORDS) * 4)   // 92224

#define CSCALE   64.0f
#define CINV     (1.0f / 64.0f)

// __device__ scratch (static: allocation-guard safe)
__device__ __half g_Bt[(size_t)OUTDIM * KD2];   // Bt[o][i*8+d-1] * 64, fp16
__device__ float  g_t[(size_t)BATCH * INDIM];   // clip(tanh(x))
__device__ float  g_bias[OUTDIM];               // sum_i C[i][o][0]

// ============================ helpers ==================================
__device__ __forceinline__ void cp_async16(uint32_t smem_dst, const void* gsrc) {
    asm volatile("cp.async.cg.shared.global [%0], [%1], 16;"
                 :: "r"(smem_dst), "l"(gsrc) : "memory");
}
__device__ __forceinline__ uint32_t smem_u32(const void* p) {
    uint32_t a;
    asm("{ .reg .u64 t; cvta.to.shared.u64 t, %1; cvt.u32.u64 %0, t; }" : "=r"(a) : "l"(p));
    return a;
}
#define MB_INIT(addr, cnt) \
    asm volatile("mbarrier.init.shared.b64 [%0], %1;" :: "r"(addr), "r"(cnt) : "memory")
#define MB_ARRIVE(addr) \
    asm volatile("{ .reg .b64 t; mbarrier.arrive.shared.b64 t, [%0]; }" :: "r"(addr) : "memory")
#define CP_MB_ARRIVE(addr) \
    asm volatile("cp.async.mbarrier.arrive.noinc.shared.b64 [%0];" :: "r"(addr) : "memory")
#define MB_WAIT(addr, parity) do {                                                       \
    uint32_t _mbar = (uint32_t)(addr);                                                   \
    uint32_t _par  = (uint32_t)(parity);                                                 \
    uint32_t _done;                                                                      \
    asm volatile("{\n\t.reg .pred p;\n\t"                                                \
        "mbarrier.try_wait.parity.acquire.cta.shared::cta.b64 p, [%1], %2;\n\t"          \
        "selp.b32 %0, 1, 0, p;\n\t}"                                                     \
        : "=r"(_done) : "r"(_mbar), "r"(_par) : "memory");                               \
    if (!_done) {                                                                        \
        asm volatile("{\n\t.reg .pred P1;\n\t"                                           \
            "WL_%=:\n\t"                                                                 \
            "mbarrier.try_wait.parity.acquire.cta.shared::cta.b64 P1, [%0], %1, 0x989680;\n\t" \
            "@P1 bra.uni WD_%=;\n\t"                                                     \
            "bra.uni WL_%=;\n\t"                                                         \
            "WD_%=:\n\t}"                                                                \
            :: "r"(_mbar), "r"(_par) : "memory");                                        \
    }                                                                                    \
} while (0)
#define BAR_GROUP(id) \
    asm volatile("bar.sync %0, 128;" :: "r"(id) : "memory")

// mma m16n8k16 row.col f32.f16.f16.f32
__device__ __forceinline__ void mma16(float* c, const uint32_t* a, uint32_t b0, uint32_t b1) {
    asm volatile(
        "mma.sync.aligned.m16n8k16.row.col.f32.f16.f16.f32 "
        "{%0,%1,%2,%3}, {%4,%5,%6,%7}, {%8,%9}, {%0,%1,%2,%3};"
        : "+f"(c[0]), "+f"(c[1]), "+f"(c[2]), "+f"(c[3])
        : "r"(a[0]), "r"(a[1]), "r"(a[2]), "r"(a[3]), "r"(b0), "r"(b1));
}
__device__ __forceinline__ void ldm4(uint32_t* r, uint32_t addr) {
    asm volatile("ldmatrix.sync.aligned.m8n8.x4.shared.b16 {%0,%1,%2,%3}, [%4];"
                 : "=r"(r[0]), "=r"(r[1]), "=r"(r[2]), "=r"(r[3]) : "r"(addr));
}

// ============ prep 1: t = clip(tanh(x)); blocks 0-3 zero g_bias ========
__global__ __launch_bounds__(256)
void prep_t_kernel(const float* __restrict__ x) {
    if (blockIdx.x < 4) g_bias[blockIdx.x * 256 + threadIdx.x] = 0.0f;
    size_t i4 = (size_t)blockIdx.x * 256 + threadIdx.x;
    const float4* src = (const float4*)x;
    float4* dst = (float4*)g_t;
    float4 v = src[i4];
    float4 r;
    r.x = fminf(fmaxf(tanhf(v.x), -0.999f), 0.999f);
    r.y = fminf(fmaxf(tanhf(v.y), -0.999f), 0.999f);
    r.z = fminf(fmaxf(tanhf(v.z), -0.999f), 0.999f);
    r.w = fminf(fmaxf(tanhf(v.w), -0.999f), 0.999f);
    dst[i4] = r;
}

// ==== prep 2: C[i,o,d>=1]*64 -> Bt[o, i*8+d-1]; d=0 -> atomic bias =====
__global__ __launch_bounds__(256)
void prep_Bt_kernel(const float* __restrict__ C) {
    int idx = blockIdx.x * 256 + threadIdx.x;   // over INDIM*OUTDIM
    int i = idx >> 10;
    int o = idx & 1023;
    const float* src = C + (size_t)i * (OUTDIM * DEG1) + (size_t)o * DEG1;
    __half* dst = g_Bt + (size_t)o * KD2 + (size_t)i * 8;
#pragma unroll
    for (int d = 1; d < DEG1; d++) dst[d - 1] = __float2half_rn(src[d] * CSCALE);
    atomicAdd(&g_bias[o], src[0]);              // T_0 == 1 contribution
}

// ============================ main GEMM ================================
__global__ __launch_bounds__(NTH, 2)
void cheby_gemm_kernel(float* __restrict__ out) {
    extern __shared__ uint32_t sm[];
    uint32_t* const Abuf = sm + MBW;                 // 2 stages
    uint32_t* const Bbuf = sm + MBW + 2 * A_WORDS;   // 3 slots
    const uint32_t mb = smem_u32(sm);                // full[s]=mb+16s, empty[s]=mb+16s+8

    const int tid  = threadIdx.x;
    const int wid  = tid >> 5;
    const int lane = tid & 31;
    const int gid  = lane >> 2;
    const int tg   = lane & 3;
    const int warp_m = wid & 1;     // 2 warps along M (64 rows)
    const int warp_n = wid >> 1;    // 4 warps along N (32 cols)
    const int m0 = blockIdx.x * TM;
    const int n0 = blockIdx.y * TN;

    // A producer mapping: group g produces the rows it consumes
    const int g   = warp_m;                       // group id
    const int gt  = (wid >> 1) * 32 + lane;       // 0..127 within group
    const int prow = g * 64 + (gt & 63);          // produced row
    const int phh  = gt >> 6;                     // k-half (32 fp16 each)

    // B copier mapping (all 256 threads)
    const int pr = tid & 127;
    const int ph = tid >> 7;

    if (tid == 0) {
#pragma unroll
        for (int s2 = 0; s2 < 3; s2++) {
            MB_INIT(mb + s2 * 16, 256);       // full
            MB_INIT(mb + s2 * 16 + 8, 256);   // empty
        }
    }
    __syncthreads();   // one-time init fence

    float acc[4][4][4];
#pragma unroll
    for (int mf = 0; mf < 4; mf++)
#pragma unroll
        for (int nf = 0; nf < 4; nf++)
#pragma unroll
            for (int q = 0; q < 4; q++) acc[mf][nf][q] = 0.0f;

    const __half* browsrc = g_Bt + (size_t)(n0 + pr) * KD2 + ph * 32;
    const uint32_t bdst_base = smem_u32(Bbuf) + (uint32_t)(pr * BSTW + ph * 16) * 4u;

    const uint32_t a_ldm_base = smem_u32(Abuf)
        + (uint32_t)(warp_m * 64 + (lane & 7) + ((lane >> 3) & 1) * 8) * ROWB
        + (uint32_t)((lane >> 4) * 16);
    const uint32_t b_ldm_base = smem_u32(Bbuf)
        + (uint32_t)(warp_n * 32 + (lane & 7) + (lane >> 4) * 8) * ROWB
        + (uint32_t)(((lane >> 3) & 1) * 16);

    // ---- prologue: fill B slot0 (jj=0), slot1 (jj=1) ----
#pragma unroll
    for (int q = 0; q < 4; q++) cp_async16(bdst_base + q * 16, browsrc + q * 8);
    CP_MB_ARRIVE(mb + 0 * 16);
#pragma unroll
    for (int q = 0; q < 4; q++)
        cp_async16(bdst_base + B_BYTES + q * 16, browsrc + KC + q * 8);
    CP_MB_ARRIVE(mb + 1 * 16);

    const float4* tsrc = (const float4*)(g_t + (size_t)(m0 + prow) * INDIM + phh * 4);
    // produce A[0] into stage 0
    {
        float4 tv = tsrc[0];
        uint32_t* dst = Abuf + prow * ASTW + phh * 16;
#pragma unroll
        for (int e = 0; e < 4; e++) {
            float t = (&tv.x)[e];
            float t2 = t + t;
            float v[8];
            v[0] = t;
            float u0 = 1.0f, u1 = t;
#pragma unroll
            for (int d = 2; d <= 8; d++) {
                float u2 = fmaf(t2, u1, -u0);
                v[d - 1] = u2;
                u0 = u1; u1 = u2;
            }
            __half2 h0 = __floats2half2_rn(v[0], v[1]);
            __half2 h1 = __floats2half2_rn(v[2], v[3]);
            __half2 h2 = __floats2half2_rn(v[4], v[5]);
            __half2 h3 = __floats2half2_rn(v[6], v[7]);
            uint4 pk;
            pk.x = *(uint32_t*)&h0; pk.y = *(uint32_t*)&h1;
            pk.z = *(uint32_t*)&h2; pk.w = *(uint32_t*)&h3;
            *(uint4*)(dst + e * 4) = pk;
        }
    }
    float4 tn = tsrc[2];           // t for producing A[1]
    BAR_GROUP(1 + g);              // group hand-off for A[0]

    int bb = 0;        // jj % 3
    int q3 = 0;        // jj / 3

#pragma unroll 1
    for (int jj = 0; jj < NITER; jj++) {
        const int s = jj & 1;

        // ---- wait B[jj] (phase = (jj/3)&1); A[s] ready via group bar ----
        MB_WAIT(mb + bb * 16, q3 & 1);

        // ---- TENSOR FIRST: ldmatrix + 64 MMAs ----
        const uint32_t a_addr0 = a_ldm_base + (uint32_t)(s * A_BYTES);
        const uint32_t b_addr0 = b_ldm_base + (uint32_t)(bb * B_BYTES);
#pragma unroll
        for (int kc = 0; kc < 4; kc++) {
            const uint32_t kb = kc * 32;
            uint32_t a[4][4];
#pragma unroll
            for (int mf = 0; mf < 4; mf++)
                ldm4(a[mf], a_addr0 + (uint32_t)(mf * 16 * ROWB) + kb);
            uint32_t b[2][4];
#pragma unroll
            for (int p = 0; p < 2; p++)
                ldm4(b[p], b_addr0 + (uint32_t)(p * 16 * ROWB) + kb);
#pragma unroll
            for (int p = 0; p < 2; p++) {
#pragma unroll
                for (int mf = 0; mf < 4; mf++) {
                    mma16(acc[mf][2 * p],     a[mf], b[p][0], b[p][1]);
                    mma16(acc[mf][2 * p + 1], a[mf], b[p][2], b[p][3]);
                }
            }
        }

        // ---- release B slot (all reads issued) ----
        MB_ARRIVE(mb + bb * 16 + 8);

        // ---- fill B[jj+2] into slot (bb+2)%3 ----
        if (jj + 2 < NITER) {
            int bb2 = (bb >= 1) ? bb - 1 : 2;          // (bb+2)%3
            if (jj >= 1) {
                int pe = ((bb == 0) ? (q3 - 1) : q3) & 1;  // ((jj-1)/3)&1
                MB_WAIT(mb + bb2 * 16 + 8, pe);
            }
            const __half* src = browsrc + (jj + 2) * KC;
            uint32_t dst = bdst_base + (uint32_t)(bb2 * B_BYTES);
#pragma unroll
            for (int q = 0; q < 4; q++) cp_async16(dst + q * 16, src + q * 8);
            CP_MB_ARRIVE(mb + bb2 * 16);
        }

        // ---- produce A[jj+1] into stage s^1; prefetch t ----
        if (jj + 1 < NITER) {
            uint32_t* dst = Abuf + (s ^ 1) * A_WORDS + prow * ASTW + phh * 16;
#pragma unroll
            for (int e = 0; e < 4; e++) {
                float t = (&tn.x)[e];
                float t2 = t + t;
                float v[8];
                v[0] = t;
                float u0 = 1.0f, u1 = t;
#pragma unroll
                for (int d = 2; d <= 8; d++) {
                    float u2 = fmaf(t2, u1, -u0);
                    v[d - 1] = u2;
                    u0 = u1; u1 = u2;
                }
                __half2 h0 = __floats2half2_rn(v[0], v[1]);
                __half2 h1 = __floats2half2_rn(v[2], v[3]);
                __half2 h2 = __floats2half2_rn(v[4], v[5]);
                __half2 h3 = __floats2half2_rn(v[6], v[7]);
                uint4 pk;
                pk.x = *(uint32_t*)&h0; pk.y = *(uint32_t*)&h1;
                pk.z = *(uint32_t*)&h2; pk.w = *(uint32_t*)&h3;
                *(uint4*)(dst + e * 4) = pk;
            }
            if (jj + 2 < NITER) tn = tsrc[(jj + 2) * 2];
        }

        // ---- group hand-off: A[jj+1] ready; A[s] reads done in group ----
        BAR_GROUP(1 + g);

        // advance jj%3 / jj/3 counters
        bb++;
        if (bb == 3) { bb = 0; q3++; }
    }

    // ---- epilogue: unscale, add T0 bias, write D ----
#pragma unroll
    for (int nf = 0; nf < 4; nf++) {
        int col = n0 + warp_n * 32 + nf * 8 + tg * 2;
        float2 bv = *(const float2*)&g_bias[col];
#pragma unroll
        for (int mf = 0; mf < 4; mf++) {
            int row = m0 + warp_m * 64 + mf * 16 + gid;
            float2* p0 = (float2*)(out + (size_t)row * OUTDIM + col);
            float2* p1 = (float2*)(out + (size_t)(row + 8) * OUTDIM + col);
            *p0 = make_float2(fmaf(acc[mf][nf][0], CINV, bv.x),
                              fmaf(acc[mf][nf][1], CINV, bv.y));
            *p1 = make_float2(fmaf(acc[mf][nf][2], CINV, bv.x),
                              fmaf(acc[mf][nf][3], CINV, bv.y));
        }
    }
}

// ============================ host launch ==============================
extern "C" void kernel_launch(void* const* d_in, const int* in_sizes, int n_in,
                              void* d_out, int out_size) {
    const float* x;
    const float* C;
    if (in_sizes[0] == BATCH * INDIM) { x = (const float*)d_in[0]; C = (const float*)d_in[1]; }
    else                              { x = (const float*)d_in[1]; C = (const float*)d_in[0]; }
    float* out = (float*)d_out;

    prep_t_kernel<<<(BATCH * INDIM) / (256 * 4), 256>>>(x);
    prep_Bt_kernel<<<(INDIM * OUTDIM) / 256, 256>>>(C);

    static int smem_set = 0;
    if (!smem_set) {
        cudaFuncSetAttribute(cheby_gemm_kernel,
                             cudaFuncAttributeMaxDynamicSharedMemorySize, SMEM_BYTES);
        smem_set = 1;
    }
    dim3 grid(BATCH / TM, OUTDIM / TN, 1);   // 64 x 8 = 512 CTAs, 2/SM
    cheby_gemm_kernel<<<grid, NTH, SMEM_BYTES>>>(out);
}

// round 9
// speedup vs baseline: 2.3196x; 1.0107x over previous
#include <cuda_runtime.h>
#include <cuda_fp16.h>
#include <cstdint>

// ============================ problem sizes ============================
#define BATCH   8192
#define INDIM   1024
#define OUTDIM  1024
#define DEG1    9
#define KD2     (INDIM * 8)         // 8192 GEMM K (d=1..8; d=0 folded into bias)
#define TM      128
#define TN      128
#define KC      64                  // 8 inputs x 8 degrees per stage
#define NITER   (KD2 / KC)          // 128
#define NTH     256                 // 8 warps, warp tile 64x32

#define ASTW    36                  // A row stride in 32-bit words
#define BSTW    36
#define ROWB    144                 // row stride in bytes
#define A_WORDS (TM * ASTW)         // 4608 words = 18432 B per stage
#define B_WORDS (TN * BSTW)
#define A_BYTES (A_WORDS * 4)
#define B_BYTES (B_WORDS * 4)
#define MBW     16                  // 64 B header for 6 mbarriers
#define SMEM_BYTES ((MBW + 2 * A_WORDS + 3 * B_WORDS) * 4)   // 92224

#define CSCALE   64.0f
#define CINV     (1.0f / 64.0f)

// __device__ scratch (static: allocation-guard safe)
__device__ __half g_Bt[(size_t)OUTDIM * KD2];   // Bt[o][i*8+d-1] * 64, fp16
__device__ float  g_t[(size_t)BATCH * INDIM];   // clip(tanh(x))
__device__ float  g_bias[OUTDIM];               // sum_i C[i][o][0]

// ============================ helpers ==================================
__device__ __forceinline__ void cp_async16(uint32_t smem_dst, const void* gsrc) {
    asm volatile("cp.async.cg.shared.global [%0], [%1], 16;"
                 :: "r"(smem_dst), "l"(gsrc) : "memory");
}
__device__ __forceinline__ uint32_t smem_u32(const void* p) {
    uint32_t a;
    asm("{ .reg .u64 t; cvta.to.shared.u64 t, %1; cvt.u32.u64 %0, t; }" : "=r"(a) : "l"(p));
    return a;
}
#define MB_INIT(addr, cnt) \
    asm volatile("mbarrier.init.shared.b64 [%0], %1;" :: "r"(addr), "r"(cnt) : "memory")
#define MB_ARRIVE(addr) \
    asm volatile("{ .reg .b64 t; mbarrier.arrive.shared.b64 t, [%0]; }" :: "r"(addr) : "memory")
#define CP_MB_ARRIVE(addr) \
    asm volatile("cp.async.mbarrier.arrive.noinc.shared.b64 [%0];" :: "r"(addr) : "memory")
#define MB_WAIT(addr, parity) do {                                                       \
    uint32_t _mbar = (uint32_t)(addr);                                                   \
    uint32_t _par  = (uint32_t)(parity);                                                 \
    uint32_t _done;                                                                      \
    asm volatile("{\n\t.reg .pred p;\n\t"                                                \
        "mbarrier.try_wait.parity.acquire.cta.shared::cta.b64 p, [%1], %2;\n\t"          \
        "selp.b32 %0, 1, 0, p;\n\t}"                                                     \
        : "=r"(_done) : "r"(_mbar), "r"(_par) : "memory");                               \
    if (!_done) {                                                                        \
        asm volatile("{\n\t.reg .pred P1;\n\t"                                           \
            "WL_%=:\n\t"                                                                 \
            "mbarrier.try_wait.parity.acquire.cta.shared::cta.b64 P1, [%0], %1, 0x989680;\n\t" \
            "@P1 bra.uni WD_%=;\n\t"                                                     \
            "bra.uni WL_%=;\n\t"                                                         \
            "WD_%=:\n\t}"                                                                \
            :: "r"(_mbar), "r"(_par) : "memory");                                        \
    }                                                                                    \
} while (0)
#define BAR_GROUP(id) \
    asm volatile("bar.sync %0, 128;" :: "r"(id) : "memory")

// mma m16n8k16 row.col f32.f16.f16.f32 — NON-volatile: pure register op,
// data-dependent on volatile ldmatrix outputs; lets the compiler interleave.
__device__ __forceinline__ void mma16(float* c, const uint32_t* a, uint32_t b0, uint32_t b1) {
    asm("mma.sync.aligned.m16n8k16.row.col.f32.f16.f16.f32 "
        "{%0,%1,%2,%3}, {%4,%5,%6,%7}, {%8,%9}, {%0,%1,%2,%3};"
        : "+f"(c[0]), "+f"(c[1]), "+f"(c[2]), "+f"(c[3])
        : "r"(a[0]), "r"(a[1]), "r"(a[2]), "r"(a[3]), "r"(b0), "r"(b1));
}
__device__ __forceinline__ void ldm4(uint32_t* r, uint32_t addr) {
    asm volatile("ldmatrix.sync.aligned.m8n8.x4.shared.b16 {%0,%1,%2,%3}, [%4];"
                 : "=r"(r[0]), "=r"(r[1]), "=r"(r[2]), "=r"(r[3]) : "r"(addr));
}

// ============ prep 1: t = clip(tanh(x)); blocks 0-3 zero g_bias ========
__global__ __launch_bounds__(256)
void prep_t_kernel(const float* __restrict__ x) {
    if (blockIdx.x < 4) g_bias[blockIdx.x * 256 + threadIdx.x] = 0.0f;
    size_t i4 = (size_t)blockIdx.x * 256 + threadIdx.x;
    const float4* src = (const float4*)x;
    float4* dst = (float4*)g_t;
    float4 v = src[i4];
    float4 r;
    r.x = fminf(fmaxf(tanhf(v.x), -0.999f), 0.999f);
    r.y = fminf(fmaxf(tanhf(v.y), -0.999f), 0.999f);
    r.z = fminf(fmaxf(tanhf(v.z), -0.999f), 0.999f);
    r.w = fminf(fmaxf(tanhf(v.w), -0.999f), 0.999f);
    dst[i4] = r;
}

// ==== prep 2: C[i,o,d>=1]*64 -> Bt[o, i*8+d-1]; d=0 -> atomic bias =====
__global__ __launch_bounds__(256)
void prep_Bt_kernel(const float* __restrict__ C) {
    int idx = blockIdx.x * 256 + threadIdx.x;   // over INDIM*OUTDIM
    int i = idx >> 10;
    int o = idx & 1023;
    const float* src = C + (size_t)i * (OUTDIM * DEG1) + (size_t)o * DEG1;
    __half* dst = g_Bt + (size_t)o * KD2 + (size_t)i * 8;
#pragma unroll
    for (int d = 1; d < DEG1; d++) dst[d - 1] = __float2half_rn(src[d] * CSCALE);
    atomicAdd(&g_bias[o], src[0]);              // T_0 == 1 contribution
}

// ============================ main GEMM ================================
__global__ __launch_bounds__(NTH, 2)
void cheby_gemm_kernel(float* __restrict__ out) {
    extern __shared__ uint32_t sm[];
    uint32_t* const Abuf = sm + MBW;                 // 2 stages
    uint32_t* const Bbuf = sm + MBW + 2 * A_WORDS;   // 3 slots
    const uint32_t mb = smem_u32(sm);                // full[s]=mb+16s, empty[s]=mb+16s+8

    const int tid  = threadIdx.x;
    const int wid  = tid >> 5;
    const int lane = tid & 31;
    const int gid  = lane >> 2;
    const int tg   = lane & 3;
    // SMSP-diverse map: group g = warps 0-3 / 4-7 (one warp of each group
    // per SMSP; with 2 CTAs -> 4 independent sync domains per SMSP)
    const int warp_m = wid >> 2;    // 2 M-halves (64 rows each)
    const int warp_n = wid & 3;     // 4 N-quarters (32 cols each)
    const int m0 = blockIdx.x * TM;
    const int n0 = blockIdx.y * TN;

    // A producer mapping: group g (tids g*128..g*128+127) produces the
    // exact rows (g*64..g*64+63) that its own warps consume
    const int g    = tid >> 7;                    // group id
    const int gt   = tid & 127;                   // 0..127 within group
    const int prow = g * 64 + (gt & 63);          // produced row
    const int phh  = gt >> 6;                     // k-half (32 fp16 each)

    // B copier mapping (all 256 threads)
    const int pr = tid & 127;
    const int ph = tid >> 7;

    if (tid == 0) {
#pragma unroll
        for (int s2 = 0; s2 < 3; s2++) {
            MB_INIT(mb + s2 * 16, 256);       // full
            MB_INIT(mb + s2 * 16 + 8, 256);   // empty
        }
    }
    __syncthreads();   // one-time init fence

    float acc[4][4][4];
#pragma unroll
    for (int mf = 0; mf < 4; mf++)
#pragma unroll
        for (int nf = 0; nf < 4; nf++)
#pragma unroll
            for (int q = 0; q < 4; q++) acc[mf][nf][q] = 0.0f;

    const __half* browsrc = g_Bt + (size_t)(n0 + pr) * KD2 + ph * 32;
    const uint32_t bdst_base = smem_u32(Bbuf) + (uint32_t)(pr * BSTW + ph * 16) * 4u;

    const uint32_t a_ldm_base = smem_u32(Abuf)
        + (uint32_t)(warp_m * 64 + (lane & 7) + ((lane >> 3) & 1) * 8) * ROWB
        + (uint32_t)((lane >> 4) * 16);
    const uint32_t b_ldm_base = smem_u32(Bbuf)
        + (uint32_t)(warp_n * 32 + (lane & 7) + (lane >> 4) * 8) * ROWB
        + (uint32_t)(((lane >> 3) & 1) * 16);

    // ---- prologue: fill B slot0 (jj=0), slot1 (jj=1) ----
#pragma unroll
    for (int q = 0; q < 4; q++) cp_async16(bdst_base + q * 16, browsrc + q * 8);
    CP_MB_ARRIVE(mb + 0 * 16);
#pragma unroll
    for (int q = 0; q < 4; q++)
        cp_async16(bdst_base + B_BYTES + q * 16, browsrc + KC + q * 8);
    CP_MB_ARRIVE(mb + 1 * 16);

    const float4* tsrc = (const float4*)(g_t + (size_t)(m0 + prow) * INDIM + phh * 4);
    // produce A[0] into stage 0
    {
        float4 tv = tsrc[0];
        uint32_t* dst = Abuf + prow * ASTW + phh * 16;
#pragma unroll
        for (int e = 0; e < 4; e++) {
            float t = (&tv.x)[e];
            float t2 = t + t;
            float v[8];
            v[0] = t;
            float u0 = 1.0f, u1 = t;
#pragma unroll
            for (int d = 2; d <= 8; d++) {
                float u2 = fmaf(t2, u1, -u0);
                v[d - 1] = u2;
                u0 = u1; u1 = u2;
            }
            __half2 h0 = __floats2half2_rn(v[0], v[1]);
            __half2 h1 = __floats2half2_rn(v[2], v[3]);
            __half2 h2 = __floats2half2_rn(v[4], v[5]);
            __half2 h3 = __floats2half2_rn(v[6], v[7]);
            uint4 pk;
            pk.x = *(uint32_t*)&h0; pk.y = *(uint32_t*)&h1;
            pk.z = *(uint32_t*)&h2; pk.w = *(uint32_t*)&h3;
            *(uint4*)(dst + e * 4) = pk;
        }
    }
    float4 tn = tsrc[2];           // t for producing A[1]
    BAR_GROUP(1 + g);              // group hand-off for A[0]

    int bb = 0;        // jj % 3
    int q3 = 0;        // jj / 3

#pragma unroll 1
    for (int jj = 0; jj < NITER; jj++) {
        const int s = jj & 1;

        // ---- wait B[jj] (phase = (jj/3)&1); A[s] ready via group bar ----
        MB_WAIT(mb + bb * 16, q3 & 1);

        // ---- TENSOR FIRST: ldmatrix + 64 MMAs ----
        const uint32_t a_addr0 = a_ldm_base + (uint32_t)(s * A_BYTES);
        const uint32_t b_addr0 = b_ldm_base + (uint32_t)(bb * B_BYTES);
#pragma unroll
        for (int kc = 0; kc < 4; kc++) {
            const uint32_t kb = kc * 32;
            uint32_t a[4][4];
#pragma unroll
            for (int mf = 0; mf < 4; mf++)
                ldm4(a[mf], a_addr0 + (uint32_t)(mf * 16 * ROWB) + kb);
            uint32_t b[2][4];
#pragma unroll
            for (int p = 0; p < 2; p++)
                ldm4(b[p], b_addr0 + (uint32_t)(p * 16 * ROWB) + kb);
#pragma unroll
            for (int p = 0; p < 2; p++) {
#pragma unroll
                for (int mf = 0; mf < 4; mf++) {
                    mma16(acc[mf][2 * p],     a[mf], b[p][0], b[p][1]);
                    mma16(acc[mf][2 * p + 1], a[mf], b[p][2], b[p][3]);
                }
            }
        }

        // ---- release B slot (all reads issued) ----
        MB_ARRIVE(mb + bb * 16 + 8);

        // ---- fill B[jj+2] into slot (bb+2)%3 ----
        if (jj + 2 < NITER) {
            int bb2 = (bb >= 1) ? bb - 1 : 2;          // (bb+2)%3
            if (jj >= 1) {
                int pe = ((bb == 0) ? (q3 - 1) : q3) & 1;  // ((jj-1)/3)&1
                MB_WAIT(mb + bb2 * 16 + 8, pe);
            }
            const __half* src = browsrc + (jj + 2) * KC;
            uint32_t dst = bdst_base + (uint32_t)(bb2 * B_BYTES);
#pragma unroll
            for (int q = 0; q < 4; q++) cp_async16(dst + q * 16, src + q * 8);
            CP_MB_ARRIVE(mb + bb2 * 16);
        }

        // ---- produce A[jj+1] into stage s^1; prefetch t ----
        if (jj + 1 < NITER) {
            uint32_t* dst = Abuf + (s ^ 1) * A_WORDS + prow * ASTW + phh * 16;
#pragma unroll
            for (int e = 0; e < 4; e++) {
                float t = (&tn.x)[e];
                float t2 = t + t;
                float v[8];
                v[0] = t;
                float u0 = 1.0f, u1 = t;
#pragma unroll
                for (int d = 2; d <= 8; d++) {
                    float u2 = fmaf(t2, u1, -u0);
                    v[d - 1] = u2;
                    u0 = u1; u1 = u2;
                }
                __half2 h0 = __floats2half2_rn(v[0], v[1]);
                __half2 h1 = __floats2half2_rn(v[2], v[3]);
                __half2 h2 = __floats2half2_rn(v[4], v[5]);
                __half2 h3 = __floats2half2_rn(v[6], v[7]);
                uint4 pk;
                pk.x = *(uint32_t*)&h0; pk.y = *(uint32_t*)&h1;
                pk.z = *(uint32_t*)&h2; pk.w = *(uint32_t*)&h3;
                *(uint4*)(dst + e * 4) = pk;
            }
            if (jj + 2 < NITER) tn = tsrc[(jj + 2) * 2];
        }

        // ---- group hand-off: A[jj+1] ready; A[s] reads done in group ----
        BAR_GROUP(1 + g);

        // advance jj%3 / jj/3 counters
        bb++;
        if (bb == 3) { bb = 0; q3++; }
    }

    // ---- epilogue: unscale, add T0 bias, write D ----
#pragma unroll
    for (int nf = 0; nf < 4; nf++) {
        int col = n0 + warp_n * 32 + nf * 8 + tg * 2;
        float2 bv = *(const float2*)&g_bias[col];
#pragma unroll
        for (int mf = 0; mf < 4; mf++) {
            int row = m0 + warp_m * 64 + mf * 16 + gid;
            float2* p0 = (float2*)(out + (size_t)row * OUTDIM + col);
            float2* p1 = (float2*)(out + (size_t)(row + 8) * OUTDIM + col);
            *p0 = make_float2(fmaf(acc[mf][nf][0], CINV, bv.x),
                              fmaf(acc[mf][nf][1], CINV, bv.y));
            *p1 = make_float2(fmaf(acc[mf][nf][2], CINV, bv.x),
                              fmaf(acc[mf][nf][3], CINV, bv.y));
        }
    }
}

// ============================ host launch ==============================
extern "C" void kernel_launch(void* const* d_in, const int* in_sizes, int n_in,
                              void* d_out, int out_size) {
    const float* x;
    const float* C;
    if (in_sizes[0] == BATCH * INDIM) { x = (const float*)d_in[0]; C = (const float*)d_in[1]; }
    else                              { x = (const float*)d_in[1]; C = (const float*)d_in[0]; }
    float* out = (float*)d_out;

    prep_t_kernel<<<(BATCH * INDIM) / (256 * 4), 256>>>(x);
    prep_Bt_kernel<<<(INDIM * OUTDIM) / 256, 256>>>(C);

    static int smem_set = 0;
    if (!smem_set) {
        cudaFuncSetAttribute(cheby_gemm_kernel,
                             cudaFuncAttributeMaxDynamicSharedMemorySize, SMEM_BYTES);
        smem_set = 1;
    }
    dim3 grid(BATCH / TM, OUTDIM / TN, 1);   // 64 x 8 = 512 CTAs, 2/SM
    cheby_gemm_kernel<<<grid, NTH, SMEM_BYTES>>>(out);
}

// round 10
// speedup vs baseline: 2.3243x; 1.0020x over previous
#include <cuda_runtime.h>
#include <cuda_fp16.h>
#include <cstdint>

// ============================ problem sizes ============================
#define BATCH   8192
#define INDIM   1024
#define OUTDIM  1024
#define DEG1    9
#define KD2     (INDIM * 8)         // 8192 GEMM K (d=1..8; d=0 folded into bias)
#define TM      128
#define TN      128
#define KC      64                  // 8 inputs x 8 degrees per stage
#define NITER   (KD2 / KC)          // 128
#define NTH     128                 // 4 warps, warp tile 64x64

#define ASTW    36                  // A row stride in 32-bit words
#define BSTW    36
#define ROWB    144                 // row stride in bytes
#define A_WORDS (TM * ASTW)         // 4608 words = 18432 B per stage
#define B_WORDS (TN * BSTW)
#define A_BYTES (A_WORDS * 4)
#define B_BYTES (B_WORDS * 4)
#define MBW     16                  // 64 B header for 6 mbarriers
#define SMEM_BYTES ((MBW + 2 * A_WORDS + 3 * B_WORDS) * 4)   // 92224

#define CSCALE   64.0f
#define CINV     (1.0f / 64.0f)

// __device__ scratch (static: allocation-guard safe)
__device__ __half g_Bt[(size_t)OUTDIM * KD2];   // Bt[o][i*8+d-1] * 64, fp16
__device__ float  g_t[(size_t)BATCH * INDIM];   // clip(tanh(x))
__device__ float  g_bias[OUTDIM];               // sum_i C[i][o][0]

// ============================ helpers ==================================
__device__ __forceinline__ void cp_async16(uint32_t smem_dst, const void* gsrc) {
    asm volatile("cp.async.cg.shared.global [%0], [%1], 16;"
                 :: "r"(smem_dst), "l"(gsrc) : "memory");
}
__device__ __forceinline__ uint32_t smem_u32(const void* p) {
    uint32_t a;
    asm("{ .reg .u64 t; cvta.to.shared.u64 t, %1; cvt.u32.u64 %0, t; }" : "=r"(a) : "l"(p));
    return a;
}
#define MB_INIT(addr, cnt) \
    asm volatile("mbarrier.init.shared.b64 [%0], %1;" :: "r"(addr), "r"(cnt) : "memory")
#define MB_ARRIVE(addr) \
    asm volatile("{ .reg .b64 t; mbarrier.arrive.shared.b64 t, [%0]; }" :: "r"(addr) : "memory")
#define CP_MB_ARRIVE(addr) \
    asm volatile("cp.async.mbarrier.arrive.noinc.shared.b64 [%0];" :: "r"(addr) : "memory")
#define MB_WAIT(addr, parity) do {                                                       \
    uint32_t _mbar = (uint32_t)(addr);                                                   \
    uint32_t _par  = (uint32_t)(parity);                                                 \
    uint32_t _done;                                                                      \
    asm volatile("{\n\t.reg .pred p;\n\t"                                                \
        "mbarrier.try_wait.parity.acquire.cta.shared::cta.b64 p, [%1], %2;\n\t"          \
        "selp.b32 %0, 1, 0, p;\n\t}"                                                     \
        : "=r"(_done) : "r"(_mbar), "r"(_par) : "memory");                               \
    if (!_done) {                                                                        \
        asm volatile("{\n\t.reg .pred P1;\n\t"                                           \
            "WL_%=:\n\t"                                                                 \
            "mbarrier.try_wait.parity.acquire.cta.shared::cta.b64 P1, [%0], %1, 0x989680;\n\t" \
            "@P1 bra.uni WD_%=;\n\t"                                                     \
            "bra.uni WL_%=;\n\t"                                                         \
            "WD_%=:\n\t}"                                                                \
            :: "r"(_mbar), "r"(_par) : "memory");                                        \
    }                                                                                    \
} while (0)

// mma m16n8k16 row.col f32.f16.f16.f32 — NON-volatile (pure register op)
__device__ __forceinline__ void mma16(float* c, const uint32_t* a, uint32_t b0, uint32_t b1) {
    asm("mma.sync.aligned.m16n8k16.row.col.f32.f16.f16.f32 "
        "{%0,%1,%2,%3}, {%4,%5,%6,%7}, {%8,%9}, {%0,%1,%2,%3};"
        : "+f"(c[0]), "+f"(c[1]), "+f"(c[2]), "+f"(c[3])
        : "r"(a[0]), "r"(a[1]), "r"(a[2]), "r"(a[3]), "r"(b0), "r"(b1));
}
__device__ __forceinline__ void ldm4(uint32_t* r, uint32_t addr) {
    asm volatile("ldmatrix.sync.aligned.m8n8.x4.shared.b16 {%0,%1,%2,%3}, [%4];"
                 : "=r"(r[0]), "=r"(r[1]), "=r"(r[2]), "=r"(r[3]) : "r"(addr));
}

// ============ prep 1: t = clip(tanh(x)); blocks 0-3 zero g_bias ========
__global__ __launch_bounds__(256)
void prep_t_kernel(const float* __restrict__ x) {
    if (blockIdx.x < 4) g_bias[blockIdx.x * 256 + threadIdx.x] = 0.0f;
    size_t i4 = (size_t)blockIdx.x * 256 + threadIdx.x;
    const float4* src = (const float4*)x;
    float4* dst = (float4*)g_t;
    float4 v = src[i4];
    float4 r;
    r.x = fminf(fmaxf(tanhf(v.x), -0.999f), 0.999f);
    r.y = fminf(fmaxf(tanhf(v.y), -0.999f), 0.999f);
    r.z = fminf(fmaxf(tanhf(v.z), -0.999f), 0.999f);
    r.w = fminf(fmaxf(tanhf(v.w), -0.999f), 0.999f);
    dst[i4] = r;
}

// ==== prep 2: C[i,o,d>=1]*64 -> Bt[o, i*8+d-1]; d=0 -> atomic bias =====
__global__ __launch_bounds__(256)
void prep_Bt_kernel(const float* __restrict__ C) {
    int idx = blockIdx.x * 256 + threadIdx.x;   // over INDIM*OUTDIM
    int i = idx >> 10;
    int o = idx & 1023;
    const float* src = C + (size_t)i * (OUTDIM * DEG1) + (size_t)o * DEG1;
    __half* dst = g_Bt + (size_t)o * KD2 + (size_t)i * 8;
#pragma unroll
    for (int d = 1; d < DEG1; d++) dst[d - 1] = __float2half_rn(src[d] * CSCALE);
    atomicAdd(&g_bias[o], src[0]);              // T_0 == 1 contribution
}

// ============================ main GEMM ================================
__global__ __launch_bounds__(NTH, 2)
void cheby_gemm_kernel(float* __restrict__ out) {
    extern __shared__ uint32_t sm[];
    uint32_t* const Abuf = sm + MBW;                 // 2 stages
    uint32_t* const Bbuf = sm + MBW + 2 * A_WORDS;   // 3 slots
    const uint32_t mb = smem_u32(sm);                // full[s]=mb+16s, empty[s]=mb+16s+8

    const int tid  = threadIdx.x;
    const int wid  = tid >> 5;
    const int lane = tid & 31;
    const int gid  = lane >> 2;
    const int tg   = lane & 3;
    const int warp_m = wid & 1;     // 2 warps along M (64 rows each)
    const int warp_n = wid >> 1;    // 2 warps along N (64 cols each)
    const int m0 = blockIdx.x * TM;
    const int n0 = blockIdx.y * TN;

    if (tid == 0) {
#pragma unroll
        for (int s2 = 0; s2 < 3; s2++) {
            MB_INIT(mb + s2 * 16, NTH);       // full
            MB_INIT(mb + s2 * 16 + 8, NTH);   // empty
        }
    }
    __syncthreads();   // one-time init fence

    float acc[4][8][4];
#pragma unroll
    for (int mf = 0; mf < 4; mf++)
#pragma unroll
        for (int nf = 0; nf < 8; nf++)
#pragma unroll
            for (int q = 0; q < 4; q++) acc[mf][nf][q] = 0.0f;

    // B copier: thread = row (128 rows x 32 words, 8 x cp16 each)
    const __half* browsrc = g_Bt + (size_t)(n0 + tid) * KD2;
    const uint32_t bdst_base = smem_u32(Bbuf) + (uint32_t)(tid * BSTW) * 4u;

    // ldmatrix per-lane base addresses
    const uint32_t a_ldm_base = smem_u32(Abuf)
        + (uint32_t)(warp_m * 64 + (lane & 7) + ((lane >> 3) & 1) * 8) * ROWB
        + (uint32_t)((lane >> 4) * 16);
    const uint32_t b_ldm_base = smem_u32(Bbuf)
        + (uint32_t)(warp_n * 64 + (lane & 7) + (lane >> 4) * 8) * ROWB
        + (uint32_t)(((lane >> 3) & 1) * 16);

    // ---- prologue: fill B slot0 (jj=0), slot1 (jj=1) ----
#pragma unroll
    for (int q = 0; q < 8; q++) cp_async16(bdst_base + q * 16, browsrc + q * 8);
    CP_MB_ARRIVE(mb + 0 * 16);
#pragma unroll
    for (int q = 0; q < 8; q++)
        cp_async16(bdst_base + B_BYTES + q * 16, browsrc + KC + q * 8);
    CP_MB_ARRIVE(mb + 1 * 16);

    // A producer: thread = row tid, full 64-wide K row (8 inputs x deg 1..8)
    const float4* tsrc = (const float4*)(g_t + (size_t)(m0 + tid) * INDIM);
    float4 t0 = tsrc[0], t1 = tsrc[1];     // inputs 0..7 for jj=0
    {
        uint32_t* dst = Abuf + tid * ASTW;
#pragma unroll
        for (int e = 0; e < 8; e++) {
            float t = (e < 4) ? (&t0.x)[e] : (&t1.x)[e - 4];
            float t2 = t + t;
            float v[8];
            v[0] = t;
            float u0 = 1.0f, u1 = t;
#pragma unroll
            for (int d = 2; d <= 8; d++) {
                float u2 = fmaf(t2, u1, -u0);
                v[d - 1] = u2;
                u0 = u1; u1 = u2;
            }
            __half2 h0 = __floats2half2_rn(v[0], v[1]);
            __half2 h1 = __floats2half2_rn(v[2], v[3]);
            __half2 h2 = __floats2half2_rn(v[4], v[5]);
            __half2 h3 = __floats2half2_rn(v[6], v[7]);
            uint4 pk;
            pk.x = *(uint32_t*)&h0; pk.y = *(uint32_t*)&h1;
            pk.z = *(uint32_t*)&h2; pk.w = *(uint32_t*)&h3;
            *(uint4*)(dst + e * 4) = pk;
        }
    }
    t0 = tsrc[2]; t1 = tsrc[3];            // t for producing A[1]
    __syncthreads();                       // A[0] visible

    int bb = 0;        // jj % 3
    int q3 = 0;        // jj / 3

#pragma unroll 1
    for (int jj = 0; jj < NITER; jj++) {
        const int s = jj & 1;

        // ---- wait B[jj] (phase = (jj/3)&1); A[s] ready via syncthreads ----
        MB_WAIT(mb + bb * 16, q3 & 1);

        const uint32_t a_addr0 = a_ldm_base + (uint32_t)(s * A_BYTES);
        const uint32_t b_addr0 = b_ldm_base + (uint32_t)(bb * B_BYTES);

        // ---- register-pipelined consume: ldm[kc+1] under mma[kc] ----
        uint32_t a[2][4][4], b[2][4][4];
#pragma unroll
        for (int mf = 0; mf < 4; mf++)
            ldm4(a[0][mf], a_addr0 + (uint32_t)(mf * 16 * ROWB));
#pragma unroll
        for (int p = 0; p < 4; p++)
            ldm4(b[0][p], b_addr0 + (uint32_t)(p * 16 * ROWB));
#pragma unroll
        for (int kc = 0; kc < 4; kc++) {
            const int cur = kc & 1, nxt = cur ^ 1;
            if (kc < 3) {
                const uint32_t kb = (kc + 1) * 32;
#pragma unroll
                for (int mf = 0; mf < 4; mf++)
                    ldm4(a[nxt][mf], a_addr0 + (uint32_t)(mf * 16 * ROWB) + kb);
#pragma unroll
                for (int p = 0; p < 4; p++)
                    ldm4(b[nxt][p], b_addr0 + (uint32_t)(p * 16 * ROWB) + kb);
            }
#pragma unroll
            for (int p = 0; p < 4; p++) {
#pragma unroll
                for (int mf = 0; mf < 4; mf++) {
                    mma16(acc[mf][2 * p],     a[cur][mf], b[cur][p][0], b[cur][p][1]);
                    mma16(acc[mf][2 * p + 1], a[cur][mf], b[cur][p][2], b[cur][p][3]);
                }
            }
        }

        // ---- release B slot (all ldm issued) ----
        MB_ARRIVE(mb + bb * 16 + 8);

        // ---- fill B[jj+2] into slot (bb+2)%3 ----
        if (jj + 2 < NITER) {
            int bb2 = (bb >= 1) ? bb - 1 : 2;          // (bb+2)%3
            if (jj >= 1) {
                int pe = ((bb == 0) ? (q3 - 1) : q3) & 1;  // ((jj-1)/3)&1
                MB_WAIT(mb + bb2 * 16 + 8, pe);
            }
            const __half* src = browsrc + (jj + 2) * KC;
            uint32_t dst = bdst_base + (uint32_t)(bb2 * B_BYTES);
#pragma unroll
            for (int q = 0; q < 8; q++) cp_async16(dst + q * 16, src + q * 8);
            CP_MB_ARRIVE(mb + bb2 * 16);
        }

        // ---- produce A[jj+1] into stage s^1 (hides under MMA drain) ----
        if (jj + 1 < NITER) {
            uint32_t* dst = Abuf + (s ^ 1) * A_WORDS + tid * ASTW;
#pragma unroll
            for (int e = 0; e < 8; e++) {
                float t = (e < 4) ? (&t0.x)[e] : (&t1.x)[e - 4];
                float t2 = t + t;
                float v[8];
                v[0] = t;
                float u0 = 1.0f, u1 = t;
#pragma unroll
                for (int d = 2; d <= 8; d++) {
                    float u2 = fmaf(t2, u1, -u0);
                    v[d - 1] = u2;
                    u0 = u1; u1 = u2;
                }
                __half2 h0 = __floats2half2_rn(v[0], v[1]);
                __half2 h1 = __floats2half2_rn(v[2], v[3]);
                __half2 h2 = __floats2half2_rn(v[4], v[5]);
                __half2 h3 = __floats2half2_rn(v[6], v[7]);
                uint4 pk;
                pk.x = *(uint32_t*)&h0; pk.y = *(uint32_t*)&h1;
                pk.z = *(uint32_t*)&h2; pk.w = *(uint32_t*)&h3;
                *(uint4*)(dst + e * 4) = pk;
            }
            if (jj + 2 < NITER) {
                t0 = tsrc[(jj + 2) * 2];
                t1 = tsrc[(jj + 2) * 2 + 1];
            }
        }

        // ---- CTA hand-off: A[jj+1] visible; A[s] reads complete ----
        __syncthreads();

        bb++;
        if (bb == 3) { bb = 0; q3++; }
    }

    // ---- epilogue: unscale, add T0 bias, write D ----
#pragma unroll
    for (int nf = 0; nf < 8; nf++) {
        int col = n0 + warp_n * 64 + nf * 8 + tg * 2;
        float2 bv = *(const float2*)&g_bias[col];
#pragma unroll
        for (int mf = 0; mf < 4; mf++) {
            int row = m0 + warp_m * 64 + mf * 16 + gid;
            float2* p0 = (float2*)(out + (size_t)row * OUTDIM + col);
            float2* p1 = (float2*)(out + (size_t)(row + 8) * OUTDIM + col);
            *p0 = make_float2(fmaf(acc[mf][nf][0], CINV, bv.x),
                              fmaf(acc[mf][nf][1], CINV, bv.y));
            *p1 = make_float2(fmaf(acc[mf][nf][2], CINV, bv.x),
                              fmaf(acc[mf][nf][3], CINV, bv.y));
        }
    }
}

// ============================ host launch ==============================
extern "C" void kernel_launch(void* const* d_in, const int* in_sizes, int n_in,
                              void* d_out, int out_size) {
    const float* x;
    const float* C;
    if (in_sizes[0] == BATCH * INDIM) { x = (const float*)d_in[0]; C = (const float*)d_in[1]; }
    else                              { x = (const float*)d_in[1]; C = (const float*)d_in[0]; }
    float* out = (float*)d_out;

    prep_t_kernel<<<(BATCH * INDIM) / (256 * 4), 256>>>(x);
    prep_Bt_kernel<<<(INDIM * OUTDIM) / 256, 256>>>(C);

    static int smem_set = 0;
    if (!smem_set) {
        cudaFuncSetAttribute(cheby_gemm_kernel,
                             cudaFuncAttributeMaxDynamicSharedMemorySize, SMEM_BYTES);
        smem_set = 1;
    }
    dim3 grid(BATCH / TM, OUTDIM / TN, 1);   // 64 x 8 = 512 CTAs, 2/SM
    cheby_gemm_kernel<<<grid, NTH, SMEM_BYTES>>>(out);
}